// round 8
// baseline (speedup 1.0000x reference)
#include <cuda_runtime.h>
#include <cuda_bf16.h>
#include <math.h>
#include <cstdint>

// Problem constants
#define BB 2
#define TT 1024
#define CC 2048
#define HH 32
#define NN 64
#define BT (BB*TT)              // 2048
#define BTC (BB*TT*CC)          // 4194304  (== CC*CC)

// ---------------------------------------------------------------------------
// Scratch (static device memory)
// ---------------------------------------------------------------------------
enum { S_XW=0, S_XA, S_XV, S_XG, S_R, S_K, S_V,
       S_DECAY, S_ASIG, S_G, S_AW, S_BW, S_KF, S_VF, S_O, N_F32 };
enum { B_XRH=0, B_XRL, B_XKH, B_XKL, B_XVH, B_XVL, B_XOH, B_XOL,
       B_WRH, B_WRL, B_WKH, B_WKL, B_WVH, B_WVL, B_WOH, B_WOL, N_BF16 };
#define BF16_BASE ((size_t)N_F32*BTC)                 // in floats
#define U_W_OFF   (BF16_BASE + (size_t)N_BF16*BTC/2)
#define U_A_OFF   (U_W_OFF + (size_t)4*BT*64)
#define U_V_OFF   (U_A_OFF + (size_t)4*BT*64)
#define U_G_OFF   (U_V_OFF + (size_t)4*BT*32)
#define BR_OFF    (U_G_OFF + (size_t)4*BT*128)
#define KR_OFF    (BR_OFF + (size_t)BB*HH*TT)
#define SCRATCH_FLOATS (KR_OFF + (size_t)BB*HH*TT)

__device__ float g_scratch[SCRATCH_FLOATS];

// ---------------------------------------------------------------------------
// PTX helpers (plain sm_103-compatible)
// ---------------------------------------------------------------------------
__device__ __forceinline__ uint32_t smem_u32(const void* p) {
    uint32_t a;
    asm("{ .reg .u64 t; cvta.to.shared.u64 t, %1; cvt.u32.u64 %0, t; }" : "=r"(a) : "l"(p));
    return a;
}
#define CP16(dst, src) \
    asm volatile("cp.async.cg.shared.global [%0], [%1], 16;" :: "r"(dst), "l"(src))
#define CP_COMMIT() asm volatile("cp.async.commit_group;" ::: "memory")
#define CP_WAIT2()  asm volatile("cp.async.wait_group 2;"  ::: "memory")
#define LDSM4(r, addr) \
    asm volatile("ldmatrix.sync.aligned.m8n8.x4.shared.b16 {%0,%1,%2,%3}, [%4];" \
        : "=r"((r)[0]), "=r"((r)[1]), "=r"((r)[2]), "=r"((r)[3]) : "r"(addr))
#define MMA16816(d, a, b0, b1) \
    asm volatile("mma.sync.aligned.m16n8k16.row.col.f32.bf16.bf16.f32 " \
        "{%0,%1,%2,%3}, {%4,%5,%6,%7}, {%8,%9}, {%0,%1,%2,%3};" \
        : "+f"((d)[0]), "+f"((d)[1]), "+f"((d)[2]), "+f"((d)[3]) \
        : "r"((a)[0]), "r"((a)[1]), "r"((a)[2]), "r"((a)[3]), "r"(b0), "r"(b1))

// ---------------------------------------------------------------------------
// hi/lo split helpers
// ---------------------------------------------------------------------------
__device__ __forceinline__ void split_hilo(float v, __nv_bfloat16& h, __nv_bfloat16& l) {
    h = __float2bfloat16(v);
    l = __float2bfloat16(v - __bfloat162float(h));
}
__device__ __forceinline__ void store_hilo4(__nv_bfloat16* hi, __nv_bfloat16* lo,
                                            size_t off, float4 v) {
    __nv_bfloat16 hv[4], lv[4];
    split_hilo(v.x, hv[0], lv[0]); split_hilo(v.y, hv[1], lv[1]);
    split_hilo(v.z, hv[2], lv[2]); split_hilo(v.w, hv[3], lv[3]);
    *(uint2*)&hi[off] = *(uint2*)hv;
    *(uint2*)&lo[off] = *(uint2*)lv;
}

// ---------------------------------------------------------------------------
// K0: batched fp32 -> bf16 hi/lo conversion (4 weights in one launch)
// ---------------------------------------------------------------------------
struct CvtJobs { const float* x[4]; __nv_bfloat16* hi[4]; __nv_bfloat16* lo[4]; };

__global__ __launch_bounds__(256) void cvt_all_kernel(CvtJobs jobs)
{
    const int z = blockIdx.y;
    size_t i = ((size_t)blockIdx.x * 256 + threadIdx.x) * 4;
    float4 v = *(const float4*)&jobs.x[z][i];
    store_hilo4(jobs.hi[z], jobs.lo[z], i, v);
}

// ---------------------------------------------------------------------------
// K1: token shift + 6-way mix
// ---------------------------------------------------------------------------
__global__ __launch_bounds__(256) void mix_kernel(
    const float* __restrict__ h, const float* __restrict__ shift,
    const float* __restrict__ mr, const float* __restrict__ mw,
    const float* __restrict__ mk, const float* __restrict__ mv,
    const float* __restrict__ ma, const float* __restrict__ mg,
    __nv_bfloat16* __restrict__ xrh, __nv_bfloat16* __restrict__ xrl,
    float* __restrict__ oxw,
    __nv_bfloat16* __restrict__ xkh, __nv_bfloat16* __restrict__ xkl,
    float* __restrict__ oxv,
    __nv_bfloat16* __restrict__ xvh, __nv_bfloat16* __restrict__ xvl,
    float* __restrict__ oxa, float* __restrict__ oxg)
{
    int gid = blockIdx.x * 256 + threadIdx.x;
    int row = gid >> 9;
    int c   = (gid & 511) << 2;
    int t   = row & (TT-1);
    int b   = row >> 10;
    size_t off = (size_t)row * CC + c;

    float4 hv = *(const float4*)&h[off];
    float4 pv;
    if (t == 0) pv = *(const float4*)&shift[(size_t)b*CC + c];
    else        pv = *(const float4*)&h[off - CC];
    float4 xx = make_float4(pv.x-hv.x, pv.y-hv.y, pv.z-hv.z, pv.w-hv.w);

#define MIXV(mvec, o)                                                 \
    {   float4 m = *(const float4*)&mvec[c];                          \
        o = make_float4(hv.x + xx.x*m.x, hv.y + xx.y*m.y,             \
                        hv.z + xx.z*m.z, hv.w + xx.w*m.w); }
    float4 vr; MIXV(mr, vr); store_hilo4(xrh, xrl, off, vr);
    float4 vw; MIXV(mw, vw); *(float4*)&oxw[off] = vw;
    float4 vk; MIXV(mk, vk); store_hilo4(xkh, xkl, off, vk);
    float4 vv; MIXV(mv, vv); *(float4*)&oxv[off] = vv; store_hilo4(xvh, xvl, off, vv);
    float4 va; MIXV(ma, va); *(float4*)&oxa[off] = va;
    float4 vg; MIXV(mg, vg); *(float4*)&oxg[off] = vg;
#undef MIXV
}

// ---------------------------------------------------------------------------
// K2: HMMA bf16x3 GEMM (batched over blockIdx.z jobs)
// ---------------------------------------------------------------------------
#define GSTAGES 3
#define TILE_A 8192              // 128 rows x 64 B
#define TILE_B 16384             // 256 rows x 64 B
#define STAGE_B (2*TILE_A + 2*TILE_B)   // 49152
#define GEMM_SMEM (GSTAGES*STAGE_B)     // 147456

struct GemmJob  { const __nv_bfloat16 *Ah, *Al, *Bh, *Bl; float* Y; };
struct GemmJobs { GemmJob j[3]; };

__device__ __forceinline__ uint32_t swz(uint32_t row, uint32_t chunk) {
    return row*64u + ((chunk ^ ((row >> 1) & 3u)) << 4);
}

__global__ __launch_bounds__(256, 1) void gemm_bf16x3(GemmJobs jobs)
{
    extern __shared__ char dynsmem[];
    const GemmJob gj = jobs.j[blockIdx.z];
    const __nv_bfloat16* __restrict__ Ahi = gj.Ah;
    const __nv_bfloat16* __restrict__ Alo = gj.Al;
    const __nv_bfloat16* __restrict__ Bhi = gj.Bh;
    const __nv_bfloat16* __restrict__ Blo = gj.Bl;
    float* __restrict__ Y = gj.Y;

    const uint32_t sb = smem_u32(dynsmem);
    const int tid  = threadIdx.x;
    const int lane = tid & 31;
    const int warp = tid >> 5;
    const int wm = warp >> 2;
    const int wn = warp & 3;
    const int bm = blockIdx.y << 7;
    const int bn = blockIdx.x << 8;

    auto load_stage = [&](int chunk, int stage) {
        const uint32_t st = sb + (uint32_t)stage * STAGE_B;
        const int k0 = chunk << 5;
#pragma unroll
        for (int i = 0; i < 2; i++) {
            int idx = tid + (i << 8);
            int row = idx >> 2, ch = idx & 3;
            uint32_t d = st + swz(row, ch);
            size_t g = (size_t)(bm + row) * CC + k0 + ch * 8;
            CP16(d,          Ahi + g);
            CP16(d + TILE_A, Alo + g);
        }
#pragma unroll
        for (int i = 0; i < 4; i++) {
            int idx = tid + (i << 8);
            int row = idx >> 2, ch = idx & 3;
            uint32_t d = st + 2*TILE_A + swz(row, ch);
            size_t g = (size_t)(bn + row) * CC + k0 + ch * 8;
            CP16(d,          Bhi + g);
            CP16(d + TILE_B, Blo + g);
        }
    };

    float acc[4][8][4];
#pragma unroll
    for (int mi=0;mi<4;mi++)
#pragma unroll
        for (int ni=0;ni<8;ni++)
#pragma unroll
            for (int j=0;j<4;j++) acc[mi][ni][j] = 0.f;

#pragma unroll
    for (int s = 0; s < GSTAGES; s++) { load_stage(s, s); CP_COMMIT(); }

    const int a_row = wm*64 + (lane & 7) + ((lane >> 3) & 1) * 8;
    const int a_ch  = (lane >> 4);
    const int b_row = wn*64 + (lane & 7) + (lane >> 4) * 8;
    const int b_ch  = ((lane >> 3) & 1);

    for (int it = 0; it < 64; it++) {
        const int stage = it % GSTAGES;
        const uint32_t st = sb + (uint32_t)stage * STAGE_B;
        CP_WAIT2();
        __syncthreads();

#pragma unroll
        for (int ks = 0; ks < 2; ks++) {
            uint32_t ah[4][4], al[4][4], b[4][4];
#pragma unroll
            for (int mi = 0; mi < 4; mi++) {
                uint32_t a = st + swz((uint32_t)(a_row + mi*16), (uint32_t)(a_ch + ks*2));
                LDSM4(ah[mi], a);
                LDSM4(al[mi], a + TILE_A);
            }
#pragma unroll
            for (int j = 0; j < 4; j++) {
                uint32_t baddr = st + 2*TILE_A +
                    swz((uint32_t)(b_row + j*16), (uint32_t)(b_ch + ks*2));
                LDSM4(b[j], baddr);
            }
#pragma unroll
            for (int mi = 0; mi < 4; mi++)
#pragma unroll
                for (int ni = 0; ni < 8; ni++)
                    MMA16816(acc[mi][ni], ah[mi], b[ni>>1][(ni&1)*2], b[ni>>1][(ni&1)*2+1]);
#pragma unroll
            for (int mi = 0; mi < 4; mi++)
#pragma unroll
                for (int ni = 0; ni < 8; ni++)
                    MMA16816(acc[mi][ni], al[mi], b[ni>>1][(ni&1)*2], b[ni>>1][(ni&1)*2+1]);
#pragma unroll
            for (int j = 0; j < 4; j++) {
                uint32_t baddr = st + 2*TILE_A + TILE_B +
                    swz((uint32_t)(b_row + j*16), (uint32_t)(b_ch + ks*2));
                LDSM4(b[j], baddr);
            }
#pragma unroll
            for (int mi = 0; mi < 4; mi++)
#pragma unroll
                for (int ni = 0; ni < 8; ni++)
                    MMA16816(acc[mi][ni], ah[mi], b[ni>>1][(ni&1)*2], b[ni>>1][(ni&1)*2+1]);
        }

        __syncthreads();
        if (it + GSTAGES < 64) load_stage(it + GSTAGES, stage);
        CP_COMMIT();
    }

    const int erow = bm + wm*64 + (lane >> 2);
    const int ecol = bn + wn*64 + (lane & 3) * 2;
#pragma unroll
    for (int mi = 0; mi < 4; mi++)
#pragma unroll
        for (int ni = 0; ni < 8; ni++) {
            size_t r0 = (size_t)(erow + mi*16) * CC + ecol + ni*8;
            *(float2*)&Y[r0]        = make_float2(acc[mi][ni][0], acc[mi][ni][1]);
            *(float2*)&Y[r0 + 8*CC] = make_float2(acc[mi][ni][2], acc[mi][ni][3]);
        }
}

// ---------------------------------------------------------------------------
// K3: batched LoRA stage 1 — 64x64 tile, 4x4 thread tile, K-split x4.
//     Upart[kp][:, col0:col0+64] = X[:, kp*512:(kp+1)*512] @ G[kp slice]
//     (activation applied in stage2 after partial sum)
// ---------------------------------------------------------------------------
struct Lora1Job  { const float* X; const float* G; float* U; int D; int col0; };
struct Lora1Jobs { Lora1Job j[5]; };

__global__ __launch_bounds__(256) void lora1_all_kernel(Lora1Jobs jobs)
{
    const Lora1Job jb = jobs.j[blockIdx.y];
    const float* __restrict__ X = jb.X;
    const float* __restrict__ G = jb.G;
    const int D = jb.D, col0 = jb.col0;
    const int kbase = blockIdx.z * 512;

    __shared__ float Xs[32][68];   // [k][row]
    __shared__ float Gs[32][64];   // [k][col]

    const int tid = threadIdx.x;
    const int bm = blockIdx.x * 64;
    const int tx = tid & 15;
    const int ty = tid >> 4;

    float4 px[2], pg[2];
    const int xrow = tid & 63;
    const int xkc0 = (tid >> 6) << 2;
    const int gkr0 = tid >> 4;
    const int gcc  = (tid & 15) << 2;

    auto gload = [&](int k0) {
#pragma unroll
        for (int i = 0; i < 2; i++) {
            px[i] = *(const float4*)&X[(size_t)(bm + xrow)*CC + k0 + xkc0 + i*16];
            if (col0 + gcc < D)
                pg[i] = *(const float4*)&G[(size_t)(k0 + gkr0 + i*16)*D + col0 + gcc];
            else
                pg[i] = make_float4(0.f, 0.f, 0.f, 0.f);
        }
    };
    auto sstore = [&]() {
#pragma unroll
        for (int i = 0; i < 2; i++) {
            int kc = xkc0 + i*16;
            Xs[kc+0][xrow] = px[i].x; Xs[kc+1][xrow] = px[i].y;
            Xs[kc+2][xrow] = px[i].z; Xs[kc+3][xrow] = px[i].w;
            *(float4*)&Gs[gkr0 + i*16][gcc] = pg[i];
        }
    };

    float acc[4][4];
#pragma unroll
    for (int i=0;i<4;i++)
#pragma unroll
        for (int j=0;j<4;j++) acc[i][j] = 0.f;

    gload(kbase); sstore(); __syncthreads();

    for (int k0 = kbase + 32; k0 <= kbase + 512; k0 += 32) {
        if (k0 < kbase + 512) gload(k0);
#pragma unroll
        for (int kk = 0; kk < 32; kk++) {
            float4 xa = *(const float4*)&Xs[kk][ty*4];
            float4 gb = *(const float4*)&Gs[kk][tx*4];
            float xv[4] = {xa.x, xa.y, xa.z, xa.w};
            float gv[4] = {gb.x, gb.y, gb.z, gb.w};
#pragma unroll
            for (int i=0;i<4;i++)
#pragma unroll
                for (int j=0;j<4;j++)
                    acc[i][j] += xv[i]*gv[j];
        }
        __syncthreads();
        if (k0 < kbase + 512) { sstore(); __syncthreads(); }
    }

    float* Up = jb.U + (size_t)blockIdx.z * BT * D;
#pragma unroll
    for (int i=0;i<4;i++) {
        int row = bm + ty*4 + i;
#pragma unroll
        for (int j=0;j<4;j++) {
            int col = col0 + tx*4 + j;
            if (col < D)
                Up[(size_t)row*D + col] = acc[i][j];
        }
    }
}

// ---------------------------------------------------------------------------
// K4: batched LoRA stage 2 + epilogue (sums 4 K-partials, applies act1)
// ---------------------------------------------------------------------------
struct Stage2Job  { const float* U; const float* V2; const float* bias;
                    float* out; const float* e1; const float* e2;
                    int D; int mode; int act1; };
struct Stage2Jobs { Stage2Job j[4]; };

__global__ __launch_bounds__(256) void stage2_all_kernel(Stage2Jobs jobs)
{
    const Stage2Job jb = jobs.j[blockIdx.z];
    const int D = jb.D, mode = jb.mode, act1 = jb.act1;

    constexpr int ROWS = 32;
    __shared__ float Us[ROWS][128];
    const int tid = threadIdx.x;
    const int row0 = blockIdx.y * ROWS;
    const int c = blockIdx.x * 256 + tid;

    {
        const size_t pstride = (size_t)BT * D;
        const int q = D >> 2;
        const int total = ROWS * q;
        for (int idx = tid; idx < total; idx += 256) {
            int rr = idx / q;
            int cc = (idx - rr*q) << 2;
            size_t o0 = (size_t)(row0+rr)*D + cc;
            float4 p0 = *(const float4*)&jb.U[o0];
            float4 p1 = *(const float4*)&jb.U[o0 + pstride];
            float4 p2 = *(const float4*)&jb.U[o0 + 2*pstride];
            float4 p3 = *(const float4*)&jb.U[o0 + 3*pstride];
            float4 s = make_float4(p0.x+p1.x+p2.x+p3.x, p0.y+p1.y+p2.y+p3.y,
                                   p0.z+p1.z+p2.z+p3.z, p0.w+p1.w+p2.w+p3.w);
            if (act1 == 1) {
                s.x = tanhf(s.x); s.y = tanhf(s.y);
                s.z = tanhf(s.z); s.w = tanhf(s.w);
            } else if (act1 == 2) {
                s.x = 1.f/(1.f+expf(-s.x)); s.y = 1.f/(1.f+expf(-s.y));
                s.z = 1.f/(1.f+expf(-s.z)); s.w = 1.f/(1.f+expf(-s.w));
            }
            *(float4*)&Us[rr][cc] = s;
        }
    }
    __syncthreads();

    float acc[ROWS];
#pragma unroll
    for (int r = 0; r < ROWS; r++) acc[r] = 0.f;

#pragma unroll 4
    for (int d0 = 0; d0 < D; d0 += 4) {
        float v0 = jb.V2[(size_t)(d0+0)*CC + c];
        float v1 = jb.V2[(size_t)(d0+1)*CC + c];
        float v2 = jb.V2[(size_t)(d0+2)*CC + c];
        float v3 = jb.V2[(size_t)(d0+3)*CC + c];
#pragma unroll
        for (int r = 0; r < ROWS; r++) {
            float4 u = *(const float4*)&Us[r][d0];
            acc[r] += u.x*v0 + u.y*v1 + u.z*v2 + u.w*v3;
        }
    }
    float bv = (mode == 3) ? 0.f : jb.bias[c];
#pragma unroll
    for (int r = 0; r < ROWS; r++) {
        size_t idx = (size_t)(row0+r)*CC + c;
        float y = acc[r] + bv;
        if (mode == 0)      jb.out[idx] = 0.6065306597126334f * (1.f/(1.f+expf(-y)));
        else if (mode == 1) jb.out[idx] = 1.f/(1.f+expf(-y));
        else if (mode == 2) {
            float s = 1.f/(1.f+expf(-y));
            float vr = jb.e1[idx];
            jb.out[idx] = vr + (jb.e2[idx]-vr)*s;
        } else              jb.out[idx] = y;
    }
}

// ---------------------------------------------------------------------------
// K5: per-(b,t,h) prep + per-step scalars br = <bw,r>, kr = <kf,r>
// ---------------------------------------------------------------------------
__global__ __launch_bounds__(256) void prep_kernel(
    const float* __restrict__ k, const float* __restrict__ r,
    const float* __restrict__ asig,
    const float* __restrict__ kkvec, const float* __restrict__ kavec,
    float* __restrict__ aw, float* __restrict__ bw, float* __restrict__ kf,
    float* __restrict__ brg, float* __restrict__ krg)
{
    const int tid = threadIdx.x;
    const int g = tid >> 6, n = tid & 63;
    const size_t head = (size_t)blockIdx.x*4 + g;
    const size_t idx = head*64 + n;
    const int c = (int)(idx & (CC-1));

    float kv = k[idx];
    float kk = kv * kkvec[c];
    float ss = kk*kk;
#pragma unroll
    for (int off=16; off; off>>=1) ss += __shfl_xor_sync(0xffffffffu, ss, off);
    __shared__ float red[8];
    if ((tid & 31)==0) red[tid>>5] = ss;
    __syncthreads();
    float tot = red[g*2] + red[g*2+1];
    float inv = 1.f / fmaxf(sqrtf(tot), 1e-12f);
    float kkn = kk * inv;
    float a = asig[idx];
    float awv = -kkn;
    float bwv = kkn * a;
    float kfv = kv + kavec[c]*(kv*a - kv);
    aw[idx] = awv;
    bw[idx] = bwv;
    kf[idx] = kfv;

    float rv = r[idx];
    float s1 = bwv*rv, s2 = kfv*rv;
#pragma unroll
    for (int off=16; off; off>>=1){
        s1 += __shfl_xor_sync(0xffffffffu, s1, off);
        s2 += __shfl_xor_sync(0xffffffffu, s2, off);
    }
    __shared__ float red2[8][2];
    if ((tid & 31)==0){ int w = tid>>5; red2[w][0]=s1; red2[w][1]=s2; }
    __syncthreads();
    if (n == 0) {
        float BR = red2[g*2][0] + red2[g*2+1][0];
        float KR = red2[g*2][1] + red2[g*2+1][1];
        int row = (int)(head >> 5);        // bt
        int hh  = (int)(head & 31);
        int bb  = row >> 10, t = row & (TT-1);
        size_t off2 = ((size_t)bb*HH + hh)*TT + t;
        brg[off2] = BR;
        krg[off2] = KR;
    }
}

// ---------------------------------------------------------------------------
// K6: WKV7 recurrence, v-split x4.
//     Lane map: vr = lane&3, kt = lane>>2 (same-address lanes in one LDS
//     phase -> smem broadcast). Super-steps of 4 with a 12-buffer cp.async
//     ring (one wait+barrier per 4 steps).
//     o_t = S_{t-1}.(d*r) + sa*<b,r> + v*<k,r>
// ---------------------------------------------------------------------------
#define WGRP 4
#define WSLOTS 3
#define WSLOT_BYTES (WGRP*6*64*4)   // 6144

__global__ __launch_bounds__(128) void wkv_kernel(
    const float* __restrict__ r, const float* __restrict__ k,
    const float* __restrict__ v, const float* __restrict__ d,
    const float* __restrict__ aw, const float* __restrict__ bw,
    const float* __restrict__ brg, const float* __restrict__ krg,
    const float* __restrict__ s0, float* __restrict__ o)
{
    const int blk = blockIdx.x;           // 0..255
    const int bh = blk >> 2;              // 0..63
    const int vq = blk & 3;
    const int b = bh >> 5, hh = bh & 31;
    const int tid = threadIdx.x;
    const int lane = tid & 31;
    const int warp = tid >> 5;
    const int vr = lane & 3;              // v-row within warp group
    const int kt = lane >> 2;             // k-eighth (0..7)
    const int koff = kt * 8;
    const int vg = vq*16 + warp*4 + vr;   // global v-row (0..63)

    __shared__ float ring[WSLOTS*WGRP][6][64];   // arr: 0=r 1=k 2=v 3=d 4=aw 5=bw
    __shared__ float brs[TT], krs[TT];

    const size_t rowbase = (size_t)b*TT*CC + hh*64;
    const uint32_t ring0 = smem_u32(ring);

    // cp.async mapping: 3 CP16 per thread per 4-step group (384 float4 total)
    const float* srcb[3];
    uint32_t doff[3];
#pragma unroll
    for (int i = 0; i < 3; i++) {
        int q = tid + i*128;              // 0..383
        int sl = q / 96, rem = q % 96;    // step-in-group, element
        int arr = rem >> 4, c4 = rem & 15;
        const float* bp = (arr==0) ? r : (arr==1) ? k : (arr==2) ? v :
                          (arr==3) ? d : (arr==4) ? aw : bw;
        srcb[i] = bp + rowbase + (size_t)sl*CC + c4*4;
        doff[i] = (uint32_t)((sl*384 + arr*64 + c4*4) * 4);
    }

    // scalar tables
    {
        const float* brp = brg + ((size_t)b*HH + hh)*TT;
        const float* krp = krg + ((size_t)b*HH + hh)*TT;
        for (int i = tid; i < TT; i += 128) { brs[i] = brp[i]; krs[i] = krp[i]; }
    }

    // state
    float S[8];
    {
        const float* sp = s0 + ((size_t)bh*64 + vg)*64 + koff;
#pragma unroll
        for (int i=0;i<8;i++) S[i] = sp[i];
    }

    // prologue: groups 0 and 1
#pragma unroll
    for (int g = 0; g < 2; g++) {
        uint32_t sb = ring0 + (uint32_t)g * WSLOT_BYTES;
#pragma unroll
        for (int i = 0; i < 3; i++)
            CP16(sb + doff[i], srcb[i] + (size_t)(g*WGRP)*CC);
        CP_COMMIT();
    }

    for (int s = 0; s < TT/WGRP; s++) {
        asm volatile("cp.async.wait_group 1;" ::: "memory");
        __syncthreads();

        // prefetch group s+2
        {
            const int gs = s + 2;
            if (gs < TT/WGRP) {
                uint32_t sb = ring0 + (uint32_t)(gs % WSLOTS) * WSLOT_BYTES;
#pragma unroll
                for (int i = 0; i < 3; i++)
                    CP16(sb + doff[i], srcb[i] + (size_t)(gs*WGRP)*CC);
            }
            CP_COMMIT();
        }

        const int slot = s % WSLOTS;
#pragma unroll
        for (int u = 0; u < WGRP; u++) {
            const int t = s*WGRP + u;
            const float* shr = ring[slot*WGRP+u][0];
            const float* shk = ring[slot*WGRP+u][1];
            const float* shv = ring[slot*WGRP+u][2];
            const float* shd = ring[slot*WGRP+u][3];
            const float* sha = ring[slot*WGRP+u][4];
            const float* shb = ring[slot*WGRP+u][5];

            float4 a40 = *(const float4*)&sha[koff];
            float4 a41 = *(const float4*)&sha[koff+4];
            float4 d40 = *(const float4*)&shd[koff];
            float4 d41 = *(const float4*)&shd[koff+4];
            float4 r40 = *(const float4*)&shr[koff];
            float4 r41 = *(const float4*)&shr[koff+4];

            float sa0, sa1, sd0, sd1;
            sa0 = S[0]*a40.x;           sa1 = S[1]*a40.y;
            sa0 += S[2]*a40.z;          sa1 += S[3]*a40.w;
            sa0 += S[4]*a41.x;          sa1 += S[5]*a41.y;
            sa0 += S[6]*a41.z;          sa1 += S[7]*a41.w;
            sd0 = S[0]*(d40.x*r40.x);   sd1 = S[1]*(d40.y*r40.y);
            sd0 += S[2]*(d40.z*r40.z);  sd1 += S[3]*(d40.w*r40.w);
            sd0 += S[4]*(d41.x*r41.x);  sd1 += S[5]*(d41.y*r41.y);
            sd0 += S[6]*(d41.z*r41.z);  sd1 += S[7]*(d41.w*r41.w);
            float sa = sa0 + sa1;
            float sd = sd0 + sd1;
            sa += __shfl_xor_sync(0xffffffffu, sa, 4);
            sd += __shfl_xor_sync(0xffffffffu, sd, 4);
            sa += __shfl_xor_sync(0xffffffffu, sa, 8);
            sd += __shfl_xor_sync(0xffffffffu, sd, 8);
            sa += __shfl_xor_sync(0xffffffffu, sa, 16);
            sd += __shfl_xor_sync(0xffffffffu, sd, 16);

            const float vt = shv[vg];
            if (kt == 0)
                o[rowbase + (size_t)t*CC + vg] = sd + sa*brs[t] + vt*krs[t];

            float4 b40 = *(const float4*)&shb[koff];
            float4 b41 = *(const float4*)&shb[koff+4];
            float4 k40 = *(const float4*)&shk[koff];
            float4 k41 = *(const float4*)&shk[koff+4];
            S[0] = S[0]*d40.x + sa*b40.x + vt*k40.x;
            S[1] = S[1]*d40.y + sa*b40.y + vt*k40.y;
            S[2] = S[2]*d40.z + sa*b40.z + vt*k40.z;
            S[3] = S[3]*d40.w + sa*b40.w + vt*k40.w;
            S[4] = S[4]*d41.x + sa*b41.x + vt*k41.x;
            S[5] = S[5]*d41.y + sa*b41.y + vt*k41.y;
            S[6] = S[6]*d41.z + sa*b41.z + vt*k41.z;
            S[7] = S[7]*d41.w + sa*b41.w + vt*k41.w;
        }
    }
}

// ---------------------------------------------------------------------------
// K7: group norm + per-head bonus + gate multiply -> bf16 hi/lo
// ---------------------------------------------------------------------------
__global__ __launch_bounds__(256) void gn_kernel(
    const float* __restrict__ o, const float* __restrict__ r,
    const float* __restrict__ kf, const float* __restrict__ vf,
    const float* __restrict__ gg, const float* __restrict__ rk,
    const float* __restrict__ gnw, const float* __restrict__ gnb,
    __nv_bfloat16* __restrict__ xoh, __nv_bfloat16* __restrict__ xol)
{
    const int tid = threadIdx.x;
    const int g = tid >> 6, n = tid & 63;
    const size_t head = (size_t)blockIdx.x*4 + g;
    const int h = (int)(head & (HH-1));
    const size_t idx = head*64 + n;
    const int c = h*64 + n;

    float ov = o[idx];
    float rv = r[idx], kv = kf[idx];
    float s1 = ov, s2 = ov*ov, s3 = rv*kv*rk[c];
#pragma unroll
    for (int off=16; off; off>>=1){
        s1 += __shfl_xor_sync(0xffffffffu, s1, off);
        s2 += __shfl_xor_sync(0xffffffffu, s2, off);
        s3 += __shfl_xor_sync(0xffffffffu, s3, off);
    }
    __shared__ float red[8][3];
    if ((tid & 31)==0){ int w = tid>>5; red[w][0]=s1; red[w][1]=s2; red[w][2]=s3; }
    __syncthreads();
    float S1 = red[g*2][0]+red[g*2+1][0];
    float S2 = red[g*2][1]+red[g*2+1][1];
    float S3 = red[g*2][2]+red[g*2+1][2];
    float mu = S1*(1.f/64.f);
    float var = S2*(1.f/64.f) - mu*mu;
    float y = (ov-mu)*rsqrtf(var + 6.4e-4f)*gnw[c] + gnb[c] + S3*vf[idx];
    float xo = y * gg[idx];
    __nv_bfloat16 hv, lv;
    split_hilo(xo, hv, lv);
    xoh[idx] = hv;
    xol[idx] = lv;
}

// ---------------------------------------------------------------------------
// Launch
// ---------------------------------------------------------------------------
extern "C" void kernel_launch(void* const* d_in, const int* in_sizes, int n_in,
                              void* d_out, int out_size)
{
    const float* h      = (const float*)d_in[0];
    const float* shift  = (const float*)d_in[1];
    const float* s0     = (const float*)d_in[2];
    const float* vfirst = (const float*)d_in[3];
    const float* x_r = (const float*)d_in[4];
    const float* x_w = (const float*)d_in[5];
    const float* x_k = (const float*)d_in[6];
    const float* x_v = (const float*)d_in[7];
    const float* x_a = (const float*)d_in[8];
    const float* x_g = (const float*)d_in[9];
    const float* w0 = (const float*)d_in[10];
    const float* w1 = (const float*)d_in[11];
    const float* w2 = (const float*)d_in[12];
    const float* a0 = (const float*)d_in[13];
    const float* a1 = (const float*)d_in[14];
    const float* a2 = (const float*)d_in[15];
    const float* v0 = (const float*)d_in[16];
    const float* v1 = (const float*)d_in[17];
    const float* v2 = (const float*)d_in[18];
    const float* g1 = (const float*)d_in[19];
    const float* g2 = (const float*)d_in[20];
    const float* k_k = (const float*)d_in[21];
    const float* k_a = (const float*)d_in[22];
    const float* r_k = (const float*)d_in[23];
    const float* W_r = (const float*)d_in[24];
    const float* W_k = (const float*)d_in[25];
    const float* W_v = (const float*)d_in[26];
    const float* W_o = (const float*)d_in[27];
    const float* gnw = (const float*)d_in[28];
    const float* gnb = (const float*)d_in[29];
    float* out = (float*)d_out;

    float* S = nullptr;
    cudaGetSymbolAddress((void**)&S, g_scratch);

    float* xw    = S + (size_t)S_XW*BTC;
    float* xa    = S + (size_t)S_XA*BTC;
    float* xv    = S + (size_t)S_XV*BTC;
    float* xg    = S + (size_t)S_XG*BTC;
    float* rb    = S + (size_t)S_R*BTC;
    float* kb    = S + (size_t)S_K*BTC;
    float* vb    = S + (size_t)S_V*BTC;
    float* decay = S + (size_t)S_DECAY*BTC;
    float* asig  = S + (size_t)S_ASIG*BTC;
    float* gbuf  = S + (size_t)S_G*BTC;
    float* awb   = S + (size_t)S_AW*BTC;
    float* bwb   = S + (size_t)S_BW*BTC;
    float* kfb   = S + (size_t)S_KF*BTC;
    float* vfb   = S + (size_t)S_VF*BTC;
    float* ob    = S + (size_t)S_O*BTC;

    __nv_bfloat16* bfb = (__nv_bfloat16*)(S + BF16_BASE);
#define BF(i) (bfb + (size_t)(i)*BTC)
    __nv_bfloat16 *xrh=BF(B_XRH), *xrl=BF(B_XRL), *xkh=BF(B_XKH), *xkl=BF(B_XKL);
    __nv_bfloat16 *xvh=BF(B_XVH), *xvl=BF(B_XVL), *xoh=BF(B_XOH), *xol=BF(B_XOL);
    __nv_bfloat16 *wrh=BF(B_WRH), *wrl=BF(B_WRL), *wkh=BF(B_WKH), *wkl=BF(B_WKL);
    __nv_bfloat16 *wvh=BF(B_WVH), *wvl=BF(B_WVL), *woh=BF(B_WOH), *wol=BF(B_WOL);
#undef BF
    float* Uw = S + U_W_OFF;  float* Ua = S + U_A_OFF;
    float* Uv = S + U_V_OFF;  float* Ug = S + U_G_OFF;
    float* brg = S + BR_OFF;  float* krg = S + KR_OFF;

    cudaFuncSetAttribute(gemm_bf16x3,
                         cudaFuncAttributeMaxDynamicSharedMemorySize, GEMM_SMEM);

    // 0. weight conversions
    CvtJobs cj;
    cj.x[0]=W_r; cj.hi[0]=wrh; cj.lo[0]=wrl;
    cj.x[1]=W_k; cj.hi[1]=wkh; cj.lo[1]=wkl;
    cj.x[2]=W_v; cj.hi[2]=wvh; cj.lo[2]=wvl;
    cj.x[3]=W_o; cj.hi[3]=woh; cj.lo[3]=wol;
    cvt_all_kernel<<<dim3(4096, 4), 256>>>(cj);

    // 1. token shift + mixes
    mix_kernel<<<4096, 256>>>(h, shift, x_r, x_w, x_k, x_v, x_a, x_g,
                              xrh, xrl, xw, xkh, xkl, xv, xvh, xvl, xa, xg);

    // 2. big r/k/v projections
    GemmJobs gj;
    gj.j[0] = { xrh, xrl, wrh, wrl, rb };
    gj.j[1] = { xkh, xkl, wkh, wkl, kb };
    gj.j[2] = { xvh, xvl, wvh, wvl, vb };
    gemm_bf16x3<<<dim3(8, 16, 3), 256, GEMM_SMEM>>>(gj);

    // 3. LoRA stage 1 (K-split x4 -> 640 CTAs)
    Lora1Jobs lj;
    lj.j[0] = { xw, w1, Uw,  64, 0 };
    lj.j[1] = { xa, a1, Ua,  64, 0 };
    lj.j[2] = { xv, v1, Uv,  32, 0 };
    lj.j[3] = { xg, g1, Ug, 128, 0 };
    lj.j[4] = { xg, g1, Ug, 128, 64 };
    lora1_all_kernel<<<dim3(32, 5, 4), 256>>>(lj);

    // 4. LoRA stage 2 + epilogues (sums partials, applies stage-1 act)
    Stage2Jobs sj;
    sj.j[0] = { Uw, w2, w0, decay, nullptr, nullptr,  64, 0, 1 };  // tanh
    sj.j[1] = { Ua, a2, a0, asig,  nullptr, nullptr,  64, 1, 0 };
    sj.j[2] = { Uv, v2, v0, vfb,   vb,      vfirst,   32, 2, 0 };
    sj.j[3] = { Ug, g2, nullptr, gbuf, nullptr, nullptr, 128, 3, 2 };  // sigmoid
    stage2_all_kernel<<<dim3(8, 64, 4), 256>>>(sj);

    // 5. kk-normalize / k lerp prep + per-step scalars
    prep_kernel<<<BT*HH/4, 256>>>(kb, rb, asig, k_k, k_a, awb, bwb, kfb, brg, krg);

    // 6. WKV7 recurrence (broadcast lane map, 4-step super-steps)
    wkv_kernel<<<BB*HH*4, 128>>>(rb, kfb, vfb, decay, awb, bwb, brg, krg, s0, ob);

    // 7. group norm + bonus + gate
    gn_kernel<<<BT*HH/4, 256>>>(ob, rb, kfb, vfb, gbuf, r_k, gnw, gnb, xoh, xol);

    // 8. output projection
    GemmJobs oj;
    oj.j[0] = { xoh, xol, woh, wol, out };
    oj.j[1] = oj.j[0];
    oj.j[2] = oj.j[0];
    gemm_bf16x3<<<dim3(8, 16, 1), 256, GEMM_SMEM>>>(oj);
}

// round 9
// speedup vs baseline: 1.2858x; 1.2858x over previous
#include <cuda_runtime.h>
#include <cuda_bf16.h>
#include <math.h>
#include <cstdint>

// Problem constants
#define BB 2
#define TT 1024
#define CC 2048
#define HH 32
#define NN 64
#define BT (BB*TT)              // 2048
#define BTC (BB*TT*CC)          // 4194304  (== CC*CC)

// ---------------------------------------------------------------------------
// Scratch (static device memory)
// ---------------------------------------------------------------------------
enum { S_XW=0, S_XA, S_XV, S_XG, S_R, S_K, S_V,
       S_DECAY, S_ASIG, S_G, S_AW, S_BW, S_KF, S_VF, S_O, S_DR, N_F32 };
enum { B_XRH=0, B_XRL, B_XKH, B_XKL, B_XVH, B_XVL, B_XOH, B_XOL,
       B_WRH, B_WRL, B_WKH, B_WKL, B_WVH, B_WVL, B_WOH, B_WOL, N_BF16 };
#define BF16_BASE ((size_t)N_F32*BTC)                 // in floats
#define U_W_OFF   (BF16_BASE + (size_t)N_BF16*BTC/2)
#define U_A_OFF   (U_W_OFF + (size_t)BT*64)
#define U_V_OFF   (U_A_OFF + (size_t)BT*64)
#define U_G_OFF   (U_V_OFF + (size_t)BT*32)
#define BR_OFF    (U_G_OFF + (size_t)BT*128)
#define KR_OFF    (BR_OFF + (size_t)BB*HH*TT)
#define SCRATCH_FLOATS (KR_OFF + (size_t)BB*HH*TT)

__device__ float g_scratch[SCRATCH_FLOATS];

// ---------------------------------------------------------------------------
// PTX helpers (plain sm_103-compatible)
// ---------------------------------------------------------------------------
__device__ __forceinline__ uint32_t smem_u32(const void* p) {
    uint32_t a;
    asm("{ .reg .u64 t; cvta.to.shared.u64 t, %1; cvt.u32.u64 %0, t; }" : "=r"(a) : "l"(p));
    return a;
}
#define CP16(dst, src) \
    asm volatile("cp.async.cg.shared.global [%0], [%1], 16;" :: "r"(dst), "l"(src))
#define CP_COMMIT() asm volatile("cp.async.commit_group;" ::: "memory")
#define CP_WAIT2()  asm volatile("cp.async.wait_group 2;"  ::: "memory")
#define LDSM4(r, addr) \
    asm volatile("ldmatrix.sync.aligned.m8n8.x4.shared.b16 {%0,%1,%2,%3}, [%4];" \
        : "=r"((r)[0]), "=r"((r)[1]), "=r"((r)[2]), "=r"((r)[3]) : "r"(addr))
#define MMA16816(d, a, b0, b1) \
    asm volatile("mma.sync.aligned.m16n8k16.row.col.f32.bf16.bf16.f32 " \
        "{%0,%1,%2,%3}, {%4,%5,%6,%7}, {%8,%9}, {%0,%1,%2,%3};" \
        : "+f"((d)[0]), "+f"((d)[1]), "+f"((d)[2]), "+f"((d)[3]) \
        : "r"((a)[0]), "r"((a)[1]), "r"((a)[2]), "r"((a)[3]), "r"(b0), "r"(b1))

// ---------------------------------------------------------------------------
// hi/lo split helpers
// ---------------------------------------------------------------------------
__device__ __forceinline__ void split_hilo(float v, __nv_bfloat16& h, __nv_bfloat16& l) {
    h = __float2bfloat16(v);
    l = __float2bfloat16(v - __bfloat162float(h));
}
__device__ __forceinline__ void store_hilo4(__nv_bfloat16* hi, __nv_bfloat16* lo,
                                            size_t off, float4 v) {
    __nv_bfloat16 hv[4], lv[4];
    split_hilo(v.x, hv[0], lv[0]); split_hilo(v.y, hv[1], lv[1]);
    split_hilo(v.z, hv[2], lv[2]); split_hilo(v.w, hv[3], lv[3]);
    *(uint2*)&hi[off] = *(uint2*)hv;
    *(uint2*)&lo[off] = *(uint2*)lv;
}

// ---------------------------------------------------------------------------
// K0: batched fp32 -> bf16 hi/lo conversion (4 weights in one launch)
// ---------------------------------------------------------------------------
struct CvtJobs { const float* x[4]; __nv_bfloat16* hi[4]; __nv_bfloat16* lo[4]; };

__global__ __launch_bounds__(256) void cvt_all_kernel(CvtJobs jobs)
{
    const int z = blockIdx.y;
    size_t i = ((size_t)blockIdx.x * 256 + threadIdx.x) * 4;
    float4 v = *(const float4*)&jobs.x[z][i];
    store_hilo4(jobs.hi[z], jobs.lo[z], i, v);
}

// ---------------------------------------------------------------------------
// K1: token shift + 6-way mix
// ---------------------------------------------------------------------------
__global__ __launch_bounds__(256) void mix_kernel(
    const float* __restrict__ h, const float* __restrict__ shift,
    const float* __restrict__ mr, const float* __restrict__ mw,
    const float* __restrict__ mk, const float* __restrict__ mv,
    const float* __restrict__ ma, const float* __restrict__ mg,
    __nv_bfloat16* __restrict__ xrh, __nv_bfloat16* __restrict__ xrl,
    float* __restrict__ oxw,
    __nv_bfloat16* __restrict__ xkh, __nv_bfloat16* __restrict__ xkl,
    float* __restrict__ oxv,
    __nv_bfloat16* __restrict__ xvh, __nv_bfloat16* __restrict__ xvl,
    float* __restrict__ oxa, float* __restrict__ oxg)
{
    int gid = blockIdx.x * 256 + threadIdx.x;
    int row = gid >> 9;
    int c   = (gid & 511) << 2;
    int t   = row & (TT-1);
    int b   = row >> 10;
    size_t off = (size_t)row * CC + c;

    float4 hv = *(const float4*)&h[off];
    float4 pv;
    if (t == 0) pv = *(const float4*)&shift[(size_t)b*CC + c];
    else        pv = *(const float4*)&h[off - CC];
    float4 xx = make_float4(pv.x-hv.x, pv.y-hv.y, pv.z-hv.z, pv.w-hv.w);

#define MIXV(mvec, o)                                                 \
    {   float4 m = *(const float4*)&mvec[c];                          \
        o = make_float4(hv.x + xx.x*m.x, hv.y + xx.y*m.y,             \
                        hv.z + xx.z*m.z, hv.w + xx.w*m.w); }
    float4 vr; MIXV(mr, vr); store_hilo4(xrh, xrl, off, vr);
    float4 vw; MIXV(mw, vw); *(float4*)&oxw[off] = vw;
    float4 vk; MIXV(mk, vk); store_hilo4(xkh, xkl, off, vk);
    float4 vv; MIXV(mv, vv); *(float4*)&oxv[off] = vv; store_hilo4(xvh, xvl, off, vv);
    float4 va; MIXV(ma, va); *(float4*)&oxa[off] = va;
    float4 vg; MIXV(mg, vg); *(float4*)&oxg[off] = vg;
#undef MIXV
}

// ---------------------------------------------------------------------------
// K2: FUSED HMMA bf16x3 GEMM + LoRA stage 1.
//     grid (8, 16, nz): z < nz_gemm -> GEMM job z (128x256 tile);
//     z >= nz_gemm -> lora column-tile jobs (fill the GEMM tail wave).
// ---------------------------------------------------------------------------
#define GSTAGES 3
#define TILE_A 8192              // 128 rows x 64 B
#define TILE_B 16384             // 256 rows x 64 B
#define STAGE_B (2*TILE_A + 2*TILE_B)   // 49152
#define GEMM_SMEM (GSTAGES*STAGE_B)     // 147456

struct GemmJob  { const __nv_bfloat16 *Ah, *Al, *Bh, *Bl; float* Y; };
struct Lora1Job { const float* X; const float* G; float* U; int D; int col0; int act; };
struct FusedJobs { GemmJob g[3]; Lora1Job l[5]; };

__device__ __forceinline__ uint32_t swz(uint32_t row, uint32_t chunk) {
    return row*64u + ((chunk ^ ((row >> 1) & 3u)) << 4);
}

__device__ void gemm_path(const GemmJob& gj, char* dynsmem)
{
    const __nv_bfloat16* __restrict__ Ahi = gj.Ah;
    const __nv_bfloat16* __restrict__ Alo = gj.Al;
    const __nv_bfloat16* __restrict__ Bhi = gj.Bh;
    const __nv_bfloat16* __restrict__ Blo = gj.Bl;
    float* __restrict__ Y = gj.Y;

    const uint32_t sb = smem_u32(dynsmem);
    const int tid  = threadIdx.x;
    const int lane = tid & 31;
    const int warp = tid >> 5;
    const int wm = warp >> 2;
    const int wn = warp & 3;
    const int bm = blockIdx.y << 7;
    const int bn = blockIdx.x << 8;

    auto load_stage = [&](int chunk, int stage) {
        const uint32_t st = sb + (uint32_t)stage * STAGE_B;
        const int k0 = chunk << 5;
#pragma unroll
        for (int i = 0; i < 2; i++) {
            int idx = tid + (i << 8);
            int row = idx >> 2, ch = idx & 3;
            uint32_t d = st + swz(row, ch);
            size_t g = (size_t)(bm + row) * CC + k0 + ch * 8;
            CP16(d,          Ahi + g);
            CP16(d + TILE_A, Alo + g);
        }
#pragma unroll
        for (int i = 0; i < 4; i++) {
            int idx = tid + (i << 8);
            int row = idx >> 2, ch = idx & 3;
            uint32_t d = st + 2*TILE_A + swz(row, ch);
            size_t g = (size_t)(bn + row) * CC + k0 + ch * 8;
            CP16(d,          Bhi + g);
            CP16(d + TILE_B, Blo + g);
        }
    };

    float acc[4][8][4];
#pragma unroll
    for (int mi=0;mi<4;mi++)
#pragma unroll
        for (int ni=0;ni<8;ni++)
#pragma unroll
            for (int j=0;j<4;j++) acc[mi][ni][j] = 0.f;

#pragma unroll
    for (int s = 0; s < GSTAGES; s++) { load_stage(s, s); CP_COMMIT(); }

    const int a_row = wm*64 + (lane & 7) + ((lane >> 3) & 1) * 8;
    const int a_ch  = (lane >> 4);
    const int b_row = wn*64 + (lane & 7) + (lane >> 4) * 8;
    const int b_ch  = ((lane >> 3) & 1);

    for (int it = 0; it < 64; it++) {
        const int stage = it % GSTAGES;
        const uint32_t st = sb + (uint32_t)stage * STAGE_B;
        CP_WAIT2();
        __syncthreads();

#pragma unroll
        for (int ks = 0; ks < 2; ks++) {
            uint32_t ah[4][4], al[4][4], b[4][4];
#pragma unroll
            for (int mi = 0; mi < 4; mi++) {
                uint32_t a = st + swz((uint32_t)(a_row + mi*16), (uint32_t)(a_ch + ks*2));
                LDSM4(ah[mi], a);
                LDSM4(al[mi], a + TILE_A);
            }
#pragma unroll
            for (int j = 0; j < 4; j++) {
                uint32_t baddr = st + 2*TILE_A +
                    swz((uint32_t)(b_row + j*16), (uint32_t)(b_ch + ks*2));
                LDSM4(b[j], baddr);
            }
#pragma unroll
            for (int mi = 0; mi < 4; mi++)
#pragma unroll
                for (int ni = 0; ni < 8; ni++)
                    MMA16816(acc[mi][ni], ah[mi], b[ni>>1][(ni&1)*2], b[ni>>1][(ni&1)*2+1]);
#pragma unroll
            for (int mi = 0; mi < 4; mi++)
#pragma unroll
                for (int ni = 0; ni < 8; ni++)
                    MMA16816(acc[mi][ni], al[mi], b[ni>>1][(ni&1)*2], b[ni>>1][(ni&1)*2+1]);
#pragma unroll
            for (int j = 0; j < 4; j++) {
                uint32_t baddr = st + 2*TILE_A + TILE_B +
                    swz((uint32_t)(b_row + j*16), (uint32_t)(b_ch + ks*2));
                LDSM4(b[j], baddr);
            }
#pragma unroll
            for (int mi = 0; mi < 4; mi++)
#pragma unroll
                for (int ni = 0; ni < 8; ni++)
                    MMA16816(acc[mi][ni], ah[mi], b[ni>>1][(ni&1)*2], b[ni>>1][(ni&1)*2+1]);
        }

        __syncthreads();
        if (it + GSTAGES < 64) load_stage(it + GSTAGES, stage);
        CP_COMMIT();
    }

    const int erow = bm + wm*64 + (lane >> 2);
    const int ecol = bn + wn*64 + (lane & 3) * 2;
#pragma unroll
    for (int mi = 0; mi < 4; mi++)
#pragma unroll
        for (int ni = 0; ni < 8; ni++) {
            size_t r0 = (size_t)(erow + mi*16) * CC + ecol + ni*8;
            *(float2*)&Y[r0]        = make_float2(acc[mi][ni][0], acc[mi][ni][1]);
            *(float2*)&Y[r0 + 8*CC] = make_float2(acc[mi][ni][2], acc[mi][ni][3]);
        }
}

__device__ void lora_path(const Lora1Job& jb, int mblk, char* dynsmem)
{
    const float* __restrict__ X = jb.X;
    const float* __restrict__ G = jb.G;
    const int D = jb.D, col0 = jb.col0, act = jb.act;

    float* Xs = (float*)dynsmem;            // [32][68]
    float* Gs = Xs + 32*68;                 // [32][64]

    const int tid = threadIdx.x;
    const int bm = mblk * 64;
    const int tx = tid & 15;
    const int ty = tid >> 4;

    float4 px[2], pg[2];
    const int xrow = tid & 63;
    const int xkc0 = (tid >> 6) << 2;
    const int gkr0 = tid >> 4;
    const int gcc  = (tid & 15) << 2;

    auto gload = [&](int k0) {
#pragma unroll
        for (int i = 0; i < 2; i++) {
            px[i] = *(const float4*)&X[(size_t)(bm + xrow)*CC + k0 + xkc0 + i*16];
            if (col0 + gcc < D)
                pg[i] = *(const float4*)&G[(size_t)(k0 + gkr0 + i*16)*D + col0 + gcc];
            else
                pg[i] = make_float4(0.f, 0.f, 0.f, 0.f);
        }
    };
    auto sstore = [&]() {
#pragma unroll
        for (int i = 0; i < 2; i++) {
            int kc = xkc0 + i*16;
            Xs[(kc+0)*68+xrow] = px[i].x; Xs[(kc+1)*68+xrow] = px[i].y;
            Xs[(kc+2)*68+xrow] = px[i].z; Xs[(kc+3)*68+xrow] = px[i].w;
            *(float4*)&Gs[(gkr0 + i*16)*64 + gcc] = pg[i];
        }
    };

    float acc[4][4];
#pragma unroll
    for (int i=0;i<4;i++)
#pragma unroll
        for (int j=0;j<4;j++) acc[i][j] = 0.f;

    gload(0); sstore(); __syncthreads();

    for (int k0 = 32; k0 <= 2048; k0 += 32) {
        if (k0 < 2048) gload(k0);
#pragma unroll
        for (int kk = 0; kk < 32; kk++) {
            float4 xa = *(const float4*)&Xs[kk*68 + ty*4];
            float4 gb = *(const float4*)&Gs[kk*64 + tx*4];
            float xv[4] = {xa.x, xa.y, xa.z, xa.w};
            float gv[4] = {gb.x, gb.y, gb.z, gb.w};
#pragma unroll
            for (int i=0;i<4;i++)
#pragma unroll
                for (int j=0;j<4;j++)
                    acc[i][j] += xv[i]*gv[j];
        }
        __syncthreads();
        if (k0 < 2048) { sstore(); __syncthreads(); }
    }

#pragma unroll
    for (int i=0;i<4;i++) {
        int row = bm + ty*4 + i;
#pragma unroll
        for (int j=0;j<4;j++) {
            int col = col0 + tx*4 + j;
            if (col < D) {
                float y = acc[i][j];
                if (act == 1) y = tanhf(y);
                else if (act == 2) y = 1.f/(1.f+expf(-y));
                jb.U[(size_t)row*D + col] = y;
            }
        }
    }
}

__global__ __launch_bounds__(256, 1) void gemm_lora_kernel(FusedJobs jobs, int nz_gemm)
{
    extern __shared__ char dynsmem[];
    const int z = blockIdx.z;
    if (z < nz_gemm) {
        gemm_path(jobs.g[z], dynsmem);
    } else {
        int lin = (z - nz_gemm)*128 + blockIdx.y*8 + blockIdx.x;
        if (lin >= 160) return;
        lora_path(jobs.l[lin >> 5], lin & 31, dynsmem);
    }
}

// ---------------------------------------------------------------------------
// K4: batched LoRA stage 2 + epilogue (4 jobs in one launch) — round-6 form
// ---------------------------------------------------------------------------
struct Stage2Job  { const float* U; const float* V2; const float* bias;
                    float* out; const float* e1; const float* e2; int D; int mode; };
struct Stage2Jobs { Stage2Job j[4]; };

__global__ __launch_bounds__(256) void stage2_all_kernel(Stage2Jobs jobs)
{
    const Stage2Job jb = jobs.j[blockIdx.z];
    const int D = jb.D, mode = jb.mode;

    constexpr int ROWS = 32;
    __shared__ float Us[ROWS][128];
    const int tid = threadIdx.x;
    const int row0 = blockIdx.y * ROWS;
    const int c = blockIdx.x * 256 + tid;

    {
        const int q = D >> 2;
        const int total = ROWS * q;
        for (int idx = tid; idx < total; idx += 256) {
            int rr = idx / q;
            int cc = (idx - rr*q) << 2;
            *(float4*)&Us[rr][cc] = *(const float4*)&jb.U[(size_t)(row0+rr)*D + cc];
        }
    }
    __syncthreads();

    float acc[ROWS];
#pragma unroll
    for (int r = 0; r < ROWS; r++) acc[r] = 0.f;

#pragma unroll 4
    for (int d0 = 0; d0 < D; d0 += 4) {
        float v0 = jb.V2[(size_t)(d0+0)*CC + c];
        float v1 = jb.V2[(size_t)(d0+1)*CC + c];
        float v2 = jb.V2[(size_t)(d0+2)*CC + c];
        float v3 = jb.V2[(size_t)(d0+3)*CC + c];
#pragma unroll
        for (int r = 0; r < ROWS; r++) {
            float4 u = *(const float4*)&Us[r][d0];
            acc[r] += u.x*v0 + u.y*v1 + u.z*v2 + u.w*v3;
        }
    }
    float bv = (mode == 3) ? 0.f : jb.bias[c];
#pragma unroll
    for (int r = 0; r < ROWS; r++) {
        size_t idx = (size_t)(row0+r)*CC + c;
        float y = acc[r] + bv;
        if (mode == 0)      jb.out[idx] = 0.6065306597126334f * (1.f/(1.f+expf(-y)));
        else if (mode == 1) jb.out[idx] = 1.f/(1.f+expf(-y));
        else if (mode == 2) {
            float s = 1.f/(1.f+expf(-y));
            float vr = jb.e1[idx];
            jb.out[idx] = vr + (jb.e2[idx]-vr)*s;
        } else              jb.out[idx] = y;
    }
}

// ---------------------------------------------------------------------------
// K5: per-(b,t,h) prep + per-step scalars + dr = decay*r
// ---------------------------------------------------------------------------
__global__ __launch_bounds__(256) void prep_kernel(
    const float* __restrict__ k, const float* __restrict__ r,
    const float* __restrict__ asig, const float* __restrict__ decay,
    const float* __restrict__ kkvec, const float* __restrict__ kavec,
    float* __restrict__ aw, float* __restrict__ bw, float* __restrict__ kf,
    float* __restrict__ drb,
    float* __restrict__ brg, float* __restrict__ krg)
{
    const int tid = threadIdx.x;
    const int g = tid >> 6, n = tid & 63;
    const size_t head = (size_t)blockIdx.x*4 + g;
    const size_t idx = head*64 + n;
    const int c = (int)(idx & (CC-1));

    float kv = k[idx];
    float kk = kv * kkvec[c];
    float ss = kk*kk;
#pragma unroll
    for (int off=16; off; off>>=1) ss += __shfl_xor_sync(0xffffffffu, ss, off);
    __shared__ float red[8];
    if ((tid & 31)==0) red[tid>>5] = ss;
    __syncthreads();
    float tot = red[g*2] + red[g*2+1];
    float inv = 1.f / fmaxf(sqrtf(tot), 1e-12f);
    float kkn = kk * inv;
    float a = asig[idx];
    float awv = -kkn;
    float bwv = kkn * a;
    float kfv = kv + kavec[c]*(kv*a - kv);
    aw[idx] = awv;
    bw[idx] = bwv;
    kf[idx] = kfv;

    float rv = r[idx];
    drb[idx] = decay[idx] * rv;

    float s1 = bwv*rv, s2 = kfv*rv;
#pragma unroll
    for (int off=16; off; off>>=1){
        s1 += __shfl_xor_sync(0xffffffffu, s1, off);
        s2 += __shfl_xor_sync(0xffffffffu, s2, off);
    }
    __shared__ float red2[8][2];
    if ((tid & 31)==0){ int w = tid>>5; red2[w][0]=s1; red2[w][1]=s2; }
    __syncthreads();
    if (n == 0) {
        float BR = red2[g*2][0] + red2[g*2+1][0];
        float KR = red2[g*2][1] + red2[g*2+1][1];
        int row = (int)(head >> 5);        // bt
        int hh  = (int)(head & 31);
        int bb  = row >> 10, t = row & (TT-1);
        size_t off2 = ((size_t)bb*HH + hh)*TT + t;
        brg[off2] = BR;
        krg[off2] = KR;
    }
}

// ---------------------------------------------------------------------------
// K6: WKV7 recurrence, v-split x4, cp.async 6-deep ring (round-6 skeleton).
//     Arrays in ring: 0=dr(d*r) 1=k 2=v 3=d 4=aw 5=bw
//     o_t = S_{t-1}.dr + sa*<b,r> + v*<k,r>  (scalars from smem tables)
//     One CP16 per (tid<96) per step instead of 3 CP4 per thread.
// ---------------------------------------------------------------------------
#define PF 6

__global__ __launch_bounds__(128) void wkv_kernel(
    const float* __restrict__ dr, const float* __restrict__ k,
    const float* __restrict__ v, const float* __restrict__ d,
    const float* __restrict__ aw, const float* __restrict__ bw,
    const float* __restrict__ brg, const float* __restrict__ krg,
    const float* __restrict__ s0, float* __restrict__ o)
{
    const int blk = blockIdx.x;           // 0..255
    const int bh = blk >> 2;              // 0..63
    const int vq = blk & 3;
    const int b = bh >> 5, hh = bh & 31;
    const int tid = threadIdx.x;
    const int vr = tid >> 3;              // 0..15
    const int kt = tid & 7;
    const int koff = kt * 8;
    const int vg = vq*16 + vr;            // global v-row

    __shared__ float ring[PF][6][64];
    __shared__ float brs[TT], krs[TT];

    const size_t rowbase = (size_t)b*TT*CC + hh*64;
    const uint32_t ring0 = smem_u32(ring);

    // CP16 mapping: threads 0..95 copy one float4 per step (6 arrays x 16)
    const float* src16 = nullptr;
    uint32_t doff16 = 0;
    if (tid < 96) {
        int arr = tid >> 4, c4 = tid & 15;
        const float* bp = (arr==0) ? dr : (arr==1) ? k : (arr==2) ? v :
                          (arr==3) ? d : (arr==4) ? aw : bw;
        src16 = bp + rowbase + c4*4;
        doff16 = (uint32_t)((arr*64 + c4*4) * 4);
    }

    // scalar tables
    {
        const float* brp = brg + ((size_t)b*HH + hh)*TT;
        const float* krp = krg + ((size_t)b*HH + hh)*TT;
        for (int i = tid; i < TT; i += 128) { brs[i] = brp[i]; krs[i] = krp[i]; }
    }

    // state
    float S[8];
    {
        const float* sp = s0 + ((size_t)bh*64 + vg)*64 + koff;
#pragma unroll
        for (int i=0;i<8;i++) S[i] = sp[i];
    }

    // prologue: prefetch steps 0..PF-2
#pragma unroll
    for (int s = 0; s < PF-1; s++) {
        if (tid < 96)
            CP16(ring0 + (uint32_t)s*(6*64*4) + doff16, src16 + (size_t)s*CC);
        CP_COMMIT();
    }

    int buf = 0;
    for (int t = 0; t < TT; t++) {
        asm volatile("cp.async.wait_group %0;" :: "n"(PF-2) : "memory");
        __syncthreads();

        // prefetch step t+PF-1 into the buffer freed by step t-1
        {
            const int ts = t + PF - 1;
            int pbuf = buf - 1; if (pbuf < 0) pbuf += PF;
            if (ts < TT && tid < 96)
                CP16(ring0 + (uint32_t)pbuf*(6*64*4) + doff16, src16 + (size_t)ts*CC);
            CP_COMMIT();
        }

        const float* shdr = ring[buf][0];
        const float* shk  = ring[buf][1];
        const float* shv  = ring[buf][2];
        const float* shd  = ring[buf][3];
        const float* sha  = ring[buf][4];
        const float* shb  = ring[buf][5];

        float4 a40 = *(const float4*)&sha[koff];
        float4 a41 = *(const float4*)&sha[koff+4];
        float4 g40 = *(const float4*)&shdr[koff];
        float4 g41 = *(const float4*)&shdr[koff+4];

        // reductions: sa = sum S*a ; sd = sum S*dr
        float sa0, sa1, sd0, sd1;
        sa0 = S[0]*a40.x;           sa1 = S[1]*a40.y;
        sa0 += S[2]*a40.z;          sa1 += S[3]*a40.w;
        sa0 += S[4]*a41.x;          sa1 += S[5]*a41.y;
        sa0 += S[6]*a41.z;          sa1 += S[7]*a41.w;
        sd0 = S[0]*g40.x;           sd1 = S[1]*g40.y;
        sd0 += S[2]*g40.z;          sd1 += S[3]*g40.w;
        sd0 += S[4]*g41.x;          sd1 += S[5]*g41.y;
        sd0 += S[6]*g41.z;          sd1 += S[7]*g41.w;
        float sa = sa0 + sa1;
        float sd = sd0 + sd1;
        sa += __shfl_xor_sync(0xffffffffu, sa, 1);
        sd += __shfl_xor_sync(0xffffffffu, sd, 1);
        sa += __shfl_xor_sync(0xffffffffu, sa, 2);
        sd += __shfl_xor_sync(0xffffffffu, sd, 2);
        sa += __shfl_xor_sync(0xffffffffu, sa, 4);
        sd += __shfl_xor_sync(0xffffffffu, sd, 4);

        const float vt = shv[vg];
        if (kt == 0)
            o[rowbase + (size_t)t*CC + vg] = sd + sa*brs[t] + vt*krs[t];

        // S update
        float4 d40 = *(const float4*)&shd[koff];
        float4 d41 = *(const float4*)&shd[koff+4];
        float4 b40 = *(const float4*)&shb[koff];
        float4 b41 = *(const float4*)&shb[koff+4];
        float4 k40 = *(const float4*)&shk[koff];
        float4 k41 = *(const float4*)&shk[koff+4];
        S[0] = S[0]*d40.x + sa*b40.x + vt*k40.x;
        S[1] = S[1]*d40.y + sa*b40.y + vt*k40.y;
        S[2] = S[2]*d40.z + sa*b40.z + vt*k40.z;
        S[3] = S[3]*d40.w + sa*b40.w + vt*k40.w;
        S[4] = S[4]*d41.x + sa*b41.x + vt*k41.x;
        S[5] = S[5]*d41.y + sa*b41.y + vt*k41.y;
        S[6] = S[6]*d41.z + sa*b41.z + vt*k41.z;
        S[7] = S[7]*d41.w + sa*b41.w + vt*k41.w;

        buf++; if (buf == PF) buf = 0;
    }
}

// ---------------------------------------------------------------------------
// K7: group norm + per-head bonus + gate multiply -> bf16 hi/lo
// ---------------------------------------------------------------------------
__global__ __launch_bounds__(256) void gn_kernel(
    const float* __restrict__ o, const float* __restrict__ r,
    const float* __restrict__ kf, const float* __restrict__ vf,
    const float* __restrict__ gg, const float* __restrict__ rk,
    const float* __restrict__ gnw, const float* __restrict__ gnb,
    __nv_bfloat16* __restrict__ xoh, __nv_bfloat16* __restrict__ xol)
{
    const int tid = threadIdx.x;
    const int g = tid >> 6, n = tid & 63;
    const size_t head = (size_t)blockIdx.x*4 + g;
    const int h = (int)(head & (HH-1));
    const size_t idx = head*64 + n;
    const int c = h*64 + n;

    float ov = o[idx];
    float rv = r[idx], kv = kf[idx];
    float s1 = ov, s2 = ov*ov, s3 = rv*kv*rk[c];
#pragma unroll
    for (int off=16; off; off>>=1){
        s1 += __shfl_xor_sync(0xffffffffu, s1, off);
        s2 += __shfl_xor_sync(0xffffffffu, s2, off);
        s3 += __shfl_xor_sync(0xffffffffu, s3, off);
    }
    __shared__ float red[8][3];
    if ((tid & 31)==0){ int w = tid>>5; red[w][0]=s1; red[w][1]=s2; red[w][2]=s3; }
    __syncthreads();
    float S1 = red[g*2][0]+red[g*2+1][0];
    float S2 = red[g*2][1]+red[g*2+1][1];
    float S3 = red[g*2][2]+red[g*2+1][2];
    float mu = S1*(1.f/64.f);
    float var = S2*(1.f/64.f) - mu*mu;
    float y = (ov-mu)*rsqrtf(var + 6.4e-4f)*gnw[c] + gnb[c] + S3*vf[idx];
    float xo = y * gg[idx];
    __nv_bfloat16 hv, lv;
    split_hilo(xo, hv, lv);
    xoh[idx] = hv;
    xol[idx] = lv;
}

// ---------------------------------------------------------------------------
// Launch
// ---------------------------------------------------------------------------
extern "C" void kernel_launch(void* const* d_in, const int* in_sizes, int n_in,
                              void* d_out, int out_size)
{
    const float* h      = (const float*)d_in[0];
    const float* shift  = (const float*)d_in[1];
    const float* s0     = (const float*)d_in[2];
    const float* vfirst = (const float*)d_in[3];
    const float* x_r = (const float*)d_in[4];
    const float* x_w = (const float*)d_in[5];
    const float* x_k = (const float*)d_in[6];
    const float* x_v = (const float*)d_in[7];
    const float* x_a = (const float*)d_in[8];
    const float* x_g = (const float*)d_in[9];
    const float* w0 = (const float*)d_in[10];
    const float* w1 = (const float*)d_in[11];
    const float* w2 = (const float*)d_in[12];
    const float* a0 = (const float*)d_in[13];
    const float* a1 = (const float*)d_in[14];
    const float* a2 = (const float*)d_in[15];
    const float* v0 = (const float*)d_in[16];
    const float* v1 = (const float*)d_in[17];
    const float* v2 = (const float*)d_in[18];
    const float* g1 = (const float*)d_in[19];
    const float* g2 = (const float*)d_in[20];
    const float* k_k = (const float*)d_in[21];
    const float* k_a = (const float*)d_in[22];
    const float* r_k = (const float*)d_in[23];
    const float* W_r = (const float*)d_in[24];
    const float* W_k = (const float*)d_in[25];
    const float* W_v = (const float*)d_in[26];
    const float* W_o = (const float*)d_in[27];
    const float* gnw = (const float*)d_in[28];
    const float* gnb = (const float*)d_in[29];
    float* out = (float*)d_out;

    float* S = nullptr;
    cudaGetSymbolAddress((void**)&S, g_scratch);

    float* xw    = S + (size_t)S_XW*BTC;
    float* xa    = S + (size_t)S_XA*BTC;
    float* xv    = S + (size_t)S_XV*BTC;
    float* xg    = S + (size_t)S_XG*BTC;
    float* rb    = S + (size_t)S_R*BTC;
    float* kb    = S + (size_t)S_K*BTC;
    float* vb    = S + (size_t)S_V*BTC;
    float* decay = S + (size_t)S_DECAY*BTC;
    float* asig  = S + (size_t)S_ASIG*BTC;
    float* gbuf  = S + (size_t)S_G*BTC;
    float* awb   = S + (size_t)S_AW*BTC;
    float* bwb   = S + (size_t)S_BW*BTC;
    float* kfb   = S + (size_t)S_KF*BTC;
    float* vfb   = S + (size_t)S_VF*BTC;
    float* ob    = S + (size_t)S_O*BTC;
    float* drb   = S + (size_t)S_DR*BTC;

    __nv_bfloat16* bfb = (__nv_bfloat16*)(S + BF16_BASE);
#define BF(i) (bfb + (size_t)(i)*BTC)
    __nv_bfloat16 *xrh=BF(B_XRH), *xrl=BF(B_XRL), *xkh=BF(B_XKH), *xkl=BF(B_XKL);
    __nv_bfloat16 *xvh=BF(B_XVH), *xvl=BF(B_XVL), *xoh=BF(B_XOH), *xol=BF(B_XOL);
    __nv_bfloat16 *wrh=BF(B_WRH), *wrl=BF(B_WRL), *wkh=BF(B_WKH), *wkl=BF(B_WKL);
    __nv_bfloat16 *wvh=BF(B_WVH), *wvl=BF(B_WVL), *woh=BF(B_WOH), *wol=BF(B_WOL);
#undef BF
    float* Uw = S + U_W_OFF;  float* Ua = S + U_A_OFF;
    float* Uv = S + U_V_OFF;  float* Ug = S + U_G_OFF;
    float* brg = S + BR_OFF;  float* krg = S + KR_OFF;

    cudaFuncSetAttribute(gemm_lora_kernel,
                         cudaFuncAttributeMaxDynamicSharedMemorySize, GEMM_SMEM);

    // 0. weight conversions
    CvtJobs cj;
    cj.x[0]=W_r; cj.hi[0]=wrh; cj.lo[0]=wrl;
    cj.x[1]=W_k; cj.hi[1]=wkh; cj.lo[1]=wkl;
    cj.x[2]=W_v; cj.hi[2]=wvh; cj.lo[2]=wvl;
    cj.x[3]=W_o; cj.hi[3]=woh; cj.lo[3]=wol;
    cvt_all_kernel<<<dim3(4096, 4), 256>>>(cj);

    // 1. token shift + mixes
    mix_kernel<<<4096, 256>>>(h, shift, x_r, x_w, x_k, x_v, x_a, x_g,
                              xrh, xrl, xw, xkh, xkl, xv, xvh, xvl, xa, xg);

    // 2+3. FUSED: r/k/v projections (z=0..2) + LoRA stage 1 (z=3..4)
    FusedJobs fj;
    fj.g[0] = { xrh, xrl, wrh, wrl, rb };
    fj.g[1] = { xkh, xkl, wkh, wkl, kb };
    fj.g[2] = { xvh, xvl, wvh, wvl, vb };
    fj.l[0] = { xw, w1, Uw,  64, 0, 1 };   // tanh
    fj.l[1] = { xa, a1, Ua,  64, 0, 0 };
    fj.l[2] = { xv, v1, Uv,  32, 0, 0 };
    fj.l[3] = { xg, g1, Ug, 128, 0, 2 };   // sigmoid
    fj.l[4] = { xg, g1, Ug, 128, 64, 2 };  // sigmoid (cols 64..127)
    gemm_lora_kernel<<<dim3(8, 16, 5), 256, GEMM_SMEM>>>(fj, 3);

    // 4. LoRA stage 2 + epilogues
    Stage2Jobs sj;
    sj.j[0] = { Uw, w2, w0, decay, nullptr, nullptr,  64, 0 };
    sj.j[1] = { Ua, a2, a0, asig,  nullptr, nullptr,  64, 1 };
    sj.j[2] = { Uv, v2, v0, vfb,   vb,      vfirst,   32, 2 };
    sj.j[3] = { Ug, g2, nullptr, gbuf, nullptr, nullptr, 128, 3 };
    stage2_all_kernel<<<dim3(8, 64, 4), 256>>>(sj);

    // 5. kk-normalize / k lerp prep + per-step scalars + dr
    prep_kernel<<<BT*HH/4, 256>>>(kb, rb, asig, decay, k_k, k_a,
                                  awb, bwb, kfb, drb, brg, krg);

    // 6. WKV7 recurrence
    wkv_kernel<<<BB*HH*4, 128>>>(drb, kfb, vfb, decay, awb, bwb, brg, krg, s0, ob);

    // 7. group norm + bonus + gate
    gn_kernel<<<BT*HH/4, 256>>>(ob, rb, kfb, vfb, gbuf, r_k, gnw, gnb, xoh, xol);

    // 8. output projection (gemm path only, z=1)
    FusedJobs oj = fj;
    oj.g[0] = { xoh, xol, woh, wol, out };
    gemm_lora_kernel<<<dim3(8, 16, 1), 256, GEMM_SMEM>>>(oj, 1);
}

// round 10
// speedup vs baseline: 1.3223x; 1.0284x over previous
#include <cuda_runtime.h>
#include <cuda_bf16.h>
#include <math.h>
#include <cstdint>

// Problem constants
#define BB 2
#define TT 1024
#define CC 2048
#define HH 32
#define NN 64
#define BT (BB*TT)              // 2048
#define BTC (BB*TT*CC)          // 4194304  (== CC*CC)

// ---------------------------------------------------------------------------
// Scratch (static device memory)
// ---------------------------------------------------------------------------
enum { S_XW=0, S_XA, S_XV, S_XG, S_R, S_K, S_V,
       S_DECAY, S_ASIG, S_G, S_AW, S_BW, S_KF, S_VF, S_O, S_DR, N_F32 };
enum { B_XRH=0, B_XRL, B_XKH, B_XKL, B_XVH, B_XVL, B_XOH, B_XOL,
       B_WRH, B_WRL, B_WKH, B_WKL, B_WVH, B_WVL, B_WOH, B_WOL, N_BF16 };
#define BF16_BASE ((size_t)N_F32*BTC)                 // in floats
#define U_OFF     (BF16_BASE + (size_t)N_BF16*BTC/2)  // bf16 U region (BT*288 floats)
#define BR_OFF    (U_OFF + (size_t)BT*288)
#define KR_OFF    (BR_OFF + (size_t)BB*HH*TT)
#define V2T_OFF   (KR_OFF + (size_t)BB*HH*TT)         // bf16 V2T region (CC*288 floats)
#define SCRATCH_FLOATS (V2T_OFF + (size_t)CC*288 + 256)

__device__ float g_scratch[SCRATCH_FLOATS];

// ---------------------------------------------------------------------------
// PTX helpers
// ---------------------------------------------------------------------------
__device__ __forceinline__ uint32_t smem_u32(const void* p) {
    uint32_t a;
    asm("{ .reg .u64 t; cvta.to.shared.u64 t, %1; cvt.u32.u64 %0, t; }" : "=r"(a) : "l"(p));
    return a;
}
#define CP16(dst, src) \
    asm volatile("cp.async.cg.shared.global [%0], [%1], 16;" :: "r"(dst), "l"(src))
#define CP_COMMIT() asm volatile("cp.async.commit_group;" ::: "memory")
#define CP_WAIT2()  asm volatile("cp.async.wait_group 2;"  ::: "memory")
#define LDSM4(r, addr) \
    asm volatile("ldmatrix.sync.aligned.m8n8.x4.shared.b16 {%0,%1,%2,%3}, [%4];" \
        : "=r"((r)[0]), "=r"((r)[1]), "=r"((r)[2]), "=r"((r)[3]) : "r"(addr))
#define MMA16816(d, a, b0, b1) \
    asm volatile("mma.sync.aligned.m16n8k16.row.col.f32.bf16.bf16.f32 " \
        "{%0,%1,%2,%3}, {%4,%5,%6,%7}, {%8,%9}, {%0,%1,%2,%3};" \
        : "+f"((d)[0]), "+f"((d)[1]), "+f"((d)[2]), "+f"((d)[3]) \
        : "r"((a)[0]), "r"((a)[1]), "r"((a)[2]), "r"((a)[3]), "r"(b0), "r"(b1))

__device__ __forceinline__ void split_hilo(float v, __nv_bfloat16& h, __nv_bfloat16& l) {
    h = __float2bfloat16(v);
    l = __float2bfloat16(v - __bfloat162float(h));
}
__device__ __forceinline__ void store_hilo4(__nv_bfloat16* hi, __nv_bfloat16* lo,
                                            size_t off, float4 v) {
    __nv_bfloat16 hv[4], lv[4];
    split_hilo(v.x, hv[0], lv[0]); split_hilo(v.y, hv[1], lv[1]);
    split_hilo(v.z, hv[2], lv[2]); split_hilo(v.w, hv[3], lv[3]);
    *(uint2*)&hi[off] = *(uint2*)hv;
    *(uint2*)&lo[off] = *(uint2*)lv;
}

// ---------------------------------------------------------------------------
// K0a: batched fp32 -> bf16 hi/lo conversion (4 big weights)
// ---------------------------------------------------------------------------
struct CvtJobs { const float* x[4]; __nv_bfloat16* hi[4]; __nv_bfloat16* lo[4]; };

__global__ __launch_bounds__(256) void cvt_all_kernel(CvtJobs jobs)
{
    const int z = blockIdx.y;
    size_t i = ((size_t)blockIdx.x * 256 + threadIdx.x) * 4;
    float4 v = *(const float4*)&jobs.x[z][i];
    store_hilo4(jobs.hi[z], jobs.lo[z], i, v);
}

// ---------------------------------------------------------------------------
// K0b: V2 transpose + hi/lo: src [D, CC] fp32 -> dst [CC, D] bf16 hi/lo
// ---------------------------------------------------------------------------
struct V2tJobs { const float* src[4]; __nv_bfloat16* dh[4]; __nv_bfloat16* dl[4]; int D[4]; };

__global__ __launch_bounds__(256) void cvt_v2t_kernel(V2tJobs jobs)
{
    const int z = blockIdx.y;
    const int D = jobs.D[z];
    int i = blockIdx.x * 256 + threadIdx.x;
    if (i >= CC * D) return;
    int c = i / D, d = i - c * D;
    float v = jobs.src[z][(size_t)d * CC + c];
    __nv_bfloat16 h, l;
    split_hilo(v, h, l);
    jobs.dh[z][i] = h;
    jobs.dl[z][i] = l;
}

// ---------------------------------------------------------------------------
// K1: token shift + 6-way mix
// ---------------------------------------------------------------------------
__global__ __launch_bounds__(256) void mix_kernel(
    const float* __restrict__ h, const float* __restrict__ shift,
    const float* __restrict__ mr, const float* __restrict__ mw,
    const float* __restrict__ mk, const float* __restrict__ mv,
    const float* __restrict__ ma, const float* __restrict__ mg,
    __nv_bfloat16* __restrict__ xrh, __nv_bfloat16* __restrict__ xrl,
    float* __restrict__ oxw,
    __nv_bfloat16* __restrict__ xkh, __nv_bfloat16* __restrict__ xkl,
    float* __restrict__ oxv,
    __nv_bfloat16* __restrict__ xvh, __nv_bfloat16* __restrict__ xvl,
    float* __restrict__ oxa, float* __restrict__ oxg)
{
    int gid = blockIdx.x * 256 + threadIdx.x;
    int row = gid >> 9;
    int c   = (gid & 511) << 2;
    int t   = row & (TT-1);
    int b   = row >> 10;
    size_t off = (size_t)row * CC + c;

    float4 hv = *(const float4*)&h[off];
    float4 pv;
    if (t == 0) pv = *(const float4*)&shift[(size_t)b*CC + c];
    else        pv = *(const float4*)&h[off - CC];
    float4 xx = make_float4(pv.x-hv.x, pv.y-hv.y, pv.z-hv.z, pv.w-hv.w);

#define MIXV(mvec, o)                                                 \
    {   float4 m = *(const float4*)&mvec[c];                          \
        o = make_float4(hv.x + xx.x*m.x, hv.y + xx.y*m.y,             \
                        hv.z + xx.z*m.z, hv.w + xx.w*m.w); }
    float4 vr; MIXV(mr, vr); store_hilo4(xrh, xrl, off, vr);
    float4 vw; MIXV(mw, vw); *(float4*)&oxw[off] = vw;
    float4 vk; MIXV(mk, vk); store_hilo4(xkh, xkl, off, vk);
    float4 vv; MIXV(mv, vv); *(float4*)&oxv[off] = vv; store_hilo4(xvh, xvl, off, vv);
    float4 va; MIXV(ma, va); *(float4*)&oxa[off] = va;
    float4 vg; MIXV(mg, vg); *(float4*)&oxg[off] = vg;
#undef MIXV
}

// ---------------------------------------------------------------------------
// K2: FUSED HMMA bf16x3 GEMM + LoRA stage 1.
// ---------------------------------------------------------------------------
#define GSTAGES 3
#define TILE_A 8192
#define TILE_B 16384
#define STAGE_B (2*TILE_A + 2*TILE_B)
#define GEMM_SMEM (GSTAGES*STAGE_B)

struct GemmJob  { const __nv_bfloat16 *Ah, *Al, *Bh, *Bl; float* Y; };
struct Lora1Job { const float* X; const float* G;
                  __nv_bfloat16* Uh; __nv_bfloat16* Ul; int D; int col0; int act; };
struct FusedJobs { GemmJob g[3]; Lora1Job l[5]; };

__device__ __forceinline__ uint32_t swz(uint32_t row, uint32_t chunk) {
    return row*64u + ((chunk ^ ((row >> 1) & 3u)) << 4);
}

__device__ void gemm_path(const GemmJob& gj, char* dynsmem)
{
    const __nv_bfloat16* __restrict__ Ahi = gj.Ah;
    const __nv_bfloat16* __restrict__ Alo = gj.Al;
    const __nv_bfloat16* __restrict__ Bhi = gj.Bh;
    const __nv_bfloat16* __restrict__ Blo = gj.Bl;
    float* __restrict__ Y = gj.Y;

    const uint32_t sb = smem_u32(dynsmem);
    const int tid  = threadIdx.x;
    const int lane = tid & 31;
    const int warp = tid >> 5;
    const int wm = warp >> 2;
    const int wn = warp & 3;
    const int bm = blockIdx.y << 7;
    const int bn = blockIdx.x << 8;

    auto load_stage = [&](int chunk, int stage) {
        const uint32_t st = sb + (uint32_t)stage * STAGE_B;
        const int k0 = chunk << 5;
#pragma unroll
        for (int i = 0; i < 2; i++) {
            int idx = tid + (i << 8);
            int row = idx >> 2, ch = idx & 3;
            uint32_t d = st + swz(row, ch);
            size_t g = (size_t)(bm + row) * CC + k0 + ch * 8;
            CP16(d,          Ahi + g);
            CP16(d + TILE_A, Alo + g);
        }
#pragma unroll
        for (int i = 0; i < 4; i++) {
            int idx = tid + (i << 8);
            int row = idx >> 2, ch = idx & 3;
            uint32_t d = st + 2*TILE_A + swz(row, ch);
            size_t g = (size_t)(bn + row) * CC + k0 + ch * 8;
            CP16(d,          Bhi + g);
            CP16(d + TILE_B, Blo + g);
        }
    };

    float acc[4][8][4];
#pragma unroll
    for (int mi=0;mi<4;mi++)
#pragma unroll
        for (int ni=0;ni<8;ni++)
#pragma unroll
            for (int j=0;j<4;j++) acc[mi][ni][j] = 0.f;

#pragma unroll
    for (int s = 0; s < GSTAGES; s++) { load_stage(s, s); CP_COMMIT(); }

    const int a_row = wm*64 + (lane & 7) + ((lane >> 3) & 1) * 8;
    const int a_ch  = (lane >> 4);
    const int b_row = wn*64 + (lane & 7) + (lane >> 4) * 8;
    const int b_ch  = ((lane >> 3) & 1);

    for (int it = 0; it < 64; it++) {
        const int stage = it % GSTAGES;
        const uint32_t st = sb + (uint32_t)stage * STAGE_B;
        CP_WAIT2();
        __syncthreads();

#pragma unroll
        for (int ks = 0; ks < 2; ks++) {
            uint32_t ah[4][4], al[4][4], b[4][4];
#pragma unroll
            for (int mi = 0; mi < 4; mi++) {
                uint32_t a = st + swz((uint32_t)(a_row + mi*16), (uint32_t)(a_ch + ks*2));
                LDSM4(ah[mi], a);
                LDSM4(al[mi], a + TILE_A);
            }
#pragma unroll
            for (int j = 0; j < 4; j++) {
                uint32_t baddr = st + 2*TILE_A +
                    swz((uint32_t)(b_row + j*16), (uint32_t)(b_ch + ks*2));
                LDSM4(b[j], baddr);
            }
#pragma unroll
            for (int mi = 0; mi < 4; mi++)
#pragma unroll
                for (int ni = 0; ni < 8; ni++)
                    MMA16816(acc[mi][ni], ah[mi], b[ni>>1][(ni&1)*2], b[ni>>1][(ni&1)*2+1]);
#pragma unroll
            for (int mi = 0; mi < 4; mi++)
#pragma unroll
                for (int ni = 0; ni < 8; ni++)
                    MMA16816(acc[mi][ni], al[mi], b[ni>>1][(ni&1)*2], b[ni>>1][(ni&1)*2+1]);
#pragma unroll
            for (int j = 0; j < 4; j++) {
                uint32_t baddr = st + 2*TILE_A + TILE_B +
                    swz((uint32_t)(b_row + j*16), (uint32_t)(b_ch + ks*2));
                LDSM4(b[j], baddr);
            }
#pragma unroll
            for (int mi = 0; mi < 4; mi++)
#pragma unroll
                for (int ni = 0; ni < 8; ni++)
                    MMA16816(acc[mi][ni], ah[mi], b[ni>>1][(ni&1)*2], b[ni>>1][(ni&1)*2+1]);
        }

        __syncthreads();
        if (it + GSTAGES < 64) load_stage(it + GSTAGES, stage);
        CP_COMMIT();
    }

    const int erow = bm + wm*64 + (lane >> 2);
    const int ecol = bn + wn*64 + (lane & 3) * 2;
#pragma unroll
    for (int mi = 0; mi < 4; mi++)
#pragma unroll
        for (int ni = 0; ni < 8; ni++) {
            size_t r0 = (size_t)(erow + mi*16) * CC + ecol + ni*8;
            *(float2*)&Y[r0]        = make_float2(acc[mi][ni][0], acc[mi][ni][1]);
            *(float2*)&Y[r0 + 8*CC] = make_float2(acc[mi][ni][2], acc[mi][ni][3]);
        }
}

__device__ void lora_path(const Lora1Job& jb, int mblk, char* dynsmem)
{
    const float* __restrict__ X = jb.X;
    const float* __restrict__ G = jb.G;
    const int D = jb.D, col0 = jb.col0, act = jb.act;

    float* Xs = (float*)dynsmem;            // [32][68]
    float* Gs = Xs + 32*68;                 // [32][64]

    const int tid = threadIdx.x;
    const int bm = mblk * 64;
    const int tx = tid & 15;
    const int ty = tid >> 4;

    float4 px[2], pg[2];
    const int xrow = tid & 63;
    const int xkc0 = (tid >> 6) << 2;
    const int gkr0 = tid >> 4;
    const int gcc  = (tid & 15) << 2;

    auto gload = [&](int k0) {
#pragma unroll
        for (int i = 0; i < 2; i++) {
            px[i] = *(const float4*)&X[(size_t)(bm + xrow)*CC + k0 + xkc0 + i*16];
            if (col0 + gcc < D)
                pg[i] = *(const float4*)&G[(size_t)(k0 + gkr0 + i*16)*D + col0 + gcc];
            else
                pg[i] = make_float4(0.f, 0.f, 0.f, 0.f);
        }
    };
    auto sstore = [&]() {
#pragma unroll
        for (int i = 0; i < 2; i++) {
            int kc = xkc0 + i*16;
            Xs[(kc+0)*68+xrow] = px[i].x; Xs[(kc+1)*68+xrow] = px[i].y;
            Xs[(kc+2)*68+xrow] = px[i].z; Xs[(kc+3)*68+xrow] = px[i].w;
            *(float4*)&Gs[(gkr0 + i*16)*64 + gcc] = pg[i];
        }
    };

    float acc[4][4];
#pragma unroll
    for (int i=0;i<4;i++)
#pragma unroll
        for (int j=0;j<4;j++) acc[i][j] = 0.f;

    gload(0); sstore(); __syncthreads();

    for (int k0 = 32; k0 <= 2048; k0 += 32) {
        if (k0 < 2048) gload(k0);
#pragma unroll
        for (int kk = 0; kk < 32; kk++) {
            float4 xa = *(const float4*)&Xs[kk*68 + ty*4];
            float4 gb = *(const float4*)&Gs[kk*64 + tx*4];
            float xv[4] = {xa.x, xa.y, xa.z, xa.w};
            float gv[4] = {gb.x, gb.y, gb.z, gb.w};
#pragma unroll
            for (int i=0;i<4;i++)
#pragma unroll
                for (int j=0;j<4;j++)
                    acc[i][j] += xv[i]*gv[j];
        }
        __syncthreads();
        if (k0 < 2048) { sstore(); __syncthreads(); }
    }

#pragma unroll
    for (int i=0;i<4;i++) {
        int row = bm + ty*4 + i;
#pragma unroll
        for (int j=0;j<4;j++) {
            int col = col0 + tx*4 + j;
            if (col < D) {
                float y = acc[i][j];
                if (act == 1) y = tanhf(y);
                else if (act == 2) y = 1.f/(1.f+expf(-y));
                __nv_bfloat16 hv, lv;
                split_hilo(y, hv, lv);
                jb.Uh[(size_t)row*D + col] = hv;
                jb.Ul[(size_t)row*D + col] = lv;
            }
        }
    }
}

__global__ __launch_bounds__(256, 1) void gemm_lora_kernel(FusedJobs jobs, int nz_gemm)
{
    extern __shared__ char dynsmem[];
    const int z = blockIdx.z;
    if (z < nz_gemm) {
        gemm_path(jobs.g[z], dynsmem);
    } else {
        int lin = (z - nz_gemm)*128 + blockIdx.y*8 + blockIdx.x;
        if (lin >= 160) return;
        lora_path(jobs.l[lin >> 5], lin & 31, dynsmem);
    }
}

// ---------------------------------------------------------------------------
// K4: stage2 on HMMA — Y[BT,CC] = (Uh+Ul)[BT,D] @ (Vh+Vl)[CC,D]^T, bf16x3
// ---------------------------------------------------------------------------
struct S2Job  { const __nv_bfloat16 *Ah, *Al, *Bh, *Bl; const float* bias;
                float* out; const float* e1; const float* e2; int D; int mode; };
struct S2Jobs { S2Job j[4]; };

__global__ __launch_bounds__(256, 1) void stage2_hmma(S2Jobs jobs)
{
    extern __shared__ char dynsmem[];
    const S2Job jb = jobs.j[blockIdx.z];
    const int D = jb.D, nk = D >> 5, mode = jb.mode;

    const uint32_t sb = smem_u32(dynsmem);
    const int tid  = threadIdx.x;
    const int lane = tid & 31;
    const int warp = tid >> 5;
    const int wm = warp >> 2;
    const int wn = warp & 3;
    const int bm = blockIdx.y << 7;
    const int bn = blockIdx.x << 8;

    auto load_stage = [&](int chunk, int stage) {
        const uint32_t st = sb + (uint32_t)stage * STAGE_B;
        const int k0 = chunk << 5;
#pragma unroll
        for (int i = 0; i < 2; i++) {
            int idx = tid + (i << 8);
            int row = idx >> 2, ch = idx & 3;
            uint32_t d = st + swz(row, ch);
            size_t g = (size_t)(bm + row) * D + k0 + ch * 8;
            CP16(d,          jb.Ah + g);
            CP16(d + TILE_A, jb.Al + g);
        }
#pragma unroll
        for (int i = 0; i < 4; i++) {
            int idx = tid + (i << 8);
            int row = idx >> 2, ch = idx & 3;
            uint32_t d = st + 2*TILE_A + swz(row, ch);
            size_t g = (size_t)(bn + row) * D + k0 + ch * 8;
            CP16(d,          jb.Bh + g);
            CP16(d + TILE_B, jb.Bl + g);
        }
    };

    float acc[4][8][4];
#pragma unroll
    for (int mi=0;mi<4;mi++)
#pragma unroll
        for (int ni=0;ni<8;ni++)
#pragma unroll
            for (int j=0;j<4;j++) acc[mi][ni][j] = 0.f;

#pragma unroll
    for (int s = 0; s < GSTAGES; s++) {
        if (s < nk) load_stage(s, s);
        CP_COMMIT();
    }

    const int a_row = wm*64 + (lane & 7) + ((lane >> 3) & 1) * 8;
    const int a_ch  = (lane >> 4);
    const int b_row = wn*64 + (lane & 7) + (lane >> 4) * 8;
    const int b_ch  = ((lane >> 3) & 1);

    for (int it = 0; it < nk; it++) {
        const int stage = it % GSTAGES;
        const uint32_t st = sb + (uint32_t)stage * STAGE_B;
        CP_WAIT2();
        __syncthreads();

#pragma unroll
        for (int ks = 0; ks < 2; ks++) {
            uint32_t ah[4][4], al[4][4], b[4][4];
#pragma unroll
            for (int mi = 0; mi < 4; mi++) {
                uint32_t a = st + swz((uint32_t)(a_row + mi*16), (uint32_t)(a_ch + ks*2));
                LDSM4(ah[mi], a);
                LDSM4(al[mi], a + TILE_A);
            }
#pragma unroll
            for (int j = 0; j < 4; j++) {
                uint32_t baddr = st + 2*TILE_A +
                    swz((uint32_t)(b_row + j*16), (uint32_t)(b_ch + ks*2));
                LDSM4(b[j], baddr);
            }
#pragma unroll
            for (int mi = 0; mi < 4; mi++)
#pragma unroll
                for (int ni = 0; ni < 8; ni++)
                    MMA16816(acc[mi][ni], ah[mi], b[ni>>1][(ni&1)*2], b[ni>>1][(ni&1)*2+1]);
#pragma unroll
            for (int mi = 0; mi < 4; mi++)
#pragma unroll
                for (int ni = 0; ni < 8; ni++)
                    MMA16816(acc[mi][ni], al[mi], b[ni>>1][(ni&1)*2], b[ni>>1][(ni&1)*2+1]);
#pragma unroll
            for (int j = 0; j < 4; j++) {
                uint32_t baddr = st + 2*TILE_A + TILE_B +
                    swz((uint32_t)(b_row + j*16), (uint32_t)(b_ch + ks*2));
                LDSM4(b[j], baddr);
            }
#pragma unroll
            for (int mi = 0; mi < 4; mi++)
#pragma unroll
                for (int ni = 0; ni < 8; ni++)
                    MMA16816(acc[mi][ni], ah[mi], b[ni>>1][(ni&1)*2], b[ni>>1][(ni&1)*2+1]);
        }

        __syncthreads();
        if (it + GSTAGES < nk) load_stage(it + GSTAGES, stage);
        CP_COMMIT();
    }

    const int erow = bm + wm*64 + (lane >> 2);
    const int ecol = bn + wn*64 + (lane & 3) * 2;
#pragma unroll
    for (int mi = 0; mi < 4; mi++)
#pragma unroll
        for (int ni = 0; ni < 8; ni++) {
            const int c = ecol + ni*8;
            size_t r0 = (size_t)(erow + mi*16) * CC + c;
            float2 p0 = make_float2(acc[mi][ni][0], acc[mi][ni][1]);
            float2 p1 = make_float2(acc[mi][ni][2], acc[mi][ni][3]);
            if (mode == 3) {
                *(float2*)&jb.out[r0]        = p0;
                *(float2*)&jb.out[r0 + 8*CC] = p1;
            } else {
                float b0 = jb.bias[c], b1 = jb.bias[c+1];
                float s00 = 1.f/(1.f+expf(-(p0.x+b0)));
                float s01 = 1.f/(1.f+expf(-(p0.y+b1)));
                float s10 = 1.f/(1.f+expf(-(p1.x+b0)));
                float s11 = 1.f/(1.f+expf(-(p1.y+b1)));
                if (mode == 0) {
                    const float e = 0.6065306597126334f;
                    *(float2*)&jb.out[r0]        = make_float2(e*s00, e*s01);
                    *(float2*)&jb.out[r0 + 8*CC] = make_float2(e*s10, e*s11);
                } else if (mode == 1) {
                    *(float2*)&jb.out[r0]        = make_float2(s00, s01);
                    *(float2*)&jb.out[r0 + 8*CC] = make_float2(s10, s11);
                } else {
                    float2 a0 = *(const float2*)&jb.e1[r0];
                    float2 f0 = *(const float2*)&jb.e2[r0];
                    float2 a1 = *(const float2*)&jb.e1[r0 + 8*CC];
                    float2 f1 = *(const float2*)&jb.e2[r0 + 8*CC];
                    *(float2*)&jb.out[r0] =
                        make_float2(a0.x + (f0.x-a0.x)*s00, a0.y + (f0.y-a0.y)*s01);
                    *(float2*)&jb.out[r0 + 8*CC] =
                        make_float2(a1.x + (f1.x-a1.x)*s10, a1.y + (f1.y-a1.y)*s11);
                }
            }
        }
}

// ---------------------------------------------------------------------------
// K5: per-(b,t,h) prep + per-step scalars + dr = decay*r
// ---------------------------------------------------------------------------
__global__ __launch_bounds__(256) void prep_kernel(
    const float* __restrict__ k, const float* __restrict__ r,
    const float* __restrict__ asig, const float* __restrict__ decay,
    const float* __restrict__ kkvec, const float* __restrict__ kavec,
    float* __restrict__ aw, float* __restrict__ bw, float* __restrict__ kf,
    float* __restrict__ drb,
    float* __restrict__ brg, float* __restrict__ krg)
{
    const int tid = threadIdx.x;
    const int g = tid >> 6, n = tid & 63;
    const size_t head = (size_t)blockIdx.x*4 + g;
    const size_t idx = head*64 + n;
    const int c = (int)(idx & (CC-1));

    float kv = k[idx];
    float kk = kv * kkvec[c];
    float ss = kk*kk;
#pragma unroll
    for (int off=16; off; off>>=1) ss += __shfl_xor_sync(0xffffffffu, ss, off);
    __shared__ float red[8];
    if ((tid & 31)==0) red[tid>>5] = ss;
    __syncthreads();
    float tot = red[g*2] + red[g*2+1];
    float inv = 1.f / fmaxf(sqrtf(tot), 1e-12f);
    float kkn = kk * inv;
    float a = asig[idx];
    float awv = -kkn;
    float bwv = kkn * a;
    float kfv = kv + kavec[c]*(kv*a - kv);
    aw[idx] = awv;
    bw[idx] = bwv;
    kf[idx] = kfv;

    float rv = r[idx];
    drb[idx] = decay[idx] * rv;

    float s1 = bwv*rv, s2 = kfv*rv;
#pragma unroll
    for (int off=16; off; off>>=1){
        s1 += __shfl_xor_sync(0xffffffffu, s1, off);
        s2 += __shfl_xor_sync(0xffffffffu, s2, off);
    }
    __shared__ float red2[8][2];
    if ((tid & 31)==0){ int w = tid>>5; red2[w][0]=s1; red2[w][1]=s2; }
    __syncthreads();
    if (n == 0) {
        float BR = red2[g*2][0] + red2[g*2+1][0];
        float KR = red2[g*2][1] + red2[g*2+1][1];
        int row = (int)(head >> 5);
        int hh  = (int)(head & 31);
        int bb  = row >> 10, t = row & (TT-1);
        size_t off2 = ((size_t)bb*HH + hh)*TT + t;
        brg[off2] = BR;
        krg[off2] = KR;
    }
}

// ---------------------------------------------------------------------------
// K6: WKV7 recurrence, v-split x4, 3 x 2-step cp.async ring slots
// ---------------------------------------------------------------------------
#define STEP_BYTES (6*64*4)   // 1536

__global__ __launch_bounds__(128) void wkv_kernel(
    const float* __restrict__ dr, const float* __restrict__ k,
    const float* __restrict__ v, const float* __restrict__ d,
    const float* __restrict__ aw, const float* __restrict__ bw,
    const float* __restrict__ brg, const float* __restrict__ krg,
    const float* __restrict__ s0, float* __restrict__ o)
{
    const int blk = blockIdx.x;
    const int bh = blk >> 2;
    const int vq = blk & 3;
    const int b = bh >> 5, hh = bh & 31;
    const int tid = threadIdx.x;
    const int vr = tid >> 3;
    const int kt = tid & 7;
    const int koff = kt * 8;
    const int vg = vq*16 + vr;

    __shared__ float ring[6][6][64];
    __shared__ float brs[TT], krs[TT];

    const size_t rowbase = (size_t)b*TT*CC + hh*64;
    const uint32_t ring0 = smem_u32(ring);

    const float* src16 = nullptr;
    uint32_t doff16 = 0;
    if (tid < 96) {
        int arr = tid >> 4, c4 = tid & 15;
        const float* bp = (arr==0) ? dr : (arr==1) ? k : (arr==2) ? v :
                          (arr==3) ? d : (arr==4) ? aw : bw;
        src16 = bp + rowbase + c4*4;
        doff16 = (uint32_t)((arr*64 + c4*4) * 4);
    }

    {
        const float* brp = brg + ((size_t)b*HH + hh)*TT;
        const float* krp = krg + ((size_t)b*HH + hh)*TT;
        for (int i = tid; i < TT; i += 128) { brs[i] = brp[i]; krs[i] = krp[i]; }
    }

    float S[8];
    {
        const float* sp = s0 + ((size_t)bh*64 + vg)*64 + koff;
#pragma unroll
        for (int i=0;i<8;i++) S[i] = sp[i];
    }

#pragma unroll
    for (int g = 0; g < 2; g++) {
        if (tid < 96) {
            uint32_t sbase = ring0 + (uint32_t)(g*2)*STEP_BYTES;
            CP16(sbase + doff16,              src16 + (size_t)(2*g)*CC);
            CP16(sbase + STEP_BYTES + doff16, src16 + (size_t)(2*g+1)*CC);
        }
        CP_COMMIT();
    }

    for (int p = 0; p < TT/2; p++) {
        asm volatile("cp.async.wait_group 1;" ::: "memory");
        __syncthreads();

        {
            const int gs = p + 2;
            if (gs < TT/2 && tid < 96) {
                uint32_t sbase = ring0 + (uint32_t)((gs % 3)*2)*STEP_BYTES;
                CP16(sbase + doff16,              src16 + (size_t)(2*gs)*CC);
                CP16(sbase + STEP_BYTES + doff16, src16 + (size_t)(2*gs+1)*CC);
            }
            CP_COMMIT();
        }

#pragma unroll
        for (int u = 0; u < 2; u++) {
            const int buf = (p % 3)*2 + u;
            const int t = 2*p + u;
            const float* shdr = ring[buf][0];
            const float* shk  = ring[buf][1];
            const float* shv  = ring[buf][2];
            const float* shd  = ring[buf][3];
            const float* sha  = ring[buf][4];
            const float* shb  = ring[buf][5];

            float4 a40 = *(const float4*)&sha[koff];
            float4 a41 = *(const float4*)&sha[koff+4];
            float4 g40 = *(const float4*)&shdr[koff];
            float4 g41 = *(const float4*)&shdr[koff+4];

            float sa0, sa1, sd0, sd1;
            sa0 = S[0]*a40.x;           sa1 = S[1]*a40.y;
            sa0 += S[2]*a40.z;          sa1 += S[3]*a40.w;
            sa0 += S[4]*a41.x;          sa1 += S[5]*a41.y;
            sa0 += S[6]*a41.z;          sa1 += S[7]*a41.w;
            sd0 = S[0]*g40.x;           sd1 = S[1]*g40.y;
            sd0 += S[2]*g40.z;          sd1 += S[3]*g40.w;
            sd0 += S[4]*g41.x;          sd1 += S[5]*g41.y;
            sd0 += S[6]*g41.z;          sd1 += S[7]*g41.w;
            float sa = sa0 + sa1;
            float sd = sd0 + sd1;
            sa += __shfl_xor_sync(0xffffffffu, sa, 1);
            sd += __shfl_xor_sync(0xffffffffu, sd, 1);
            sa += __shfl_xor_sync(0xffffffffu, sa, 2);
            sd += __shfl_xor_sync(0xffffffffu, sd, 2);
            sa += __shfl_xor_sync(0xffffffffu, sa, 4);
            sd += __shfl_xor_sync(0xffffffffu, sd, 4);

            const float vt = shv[vg];
            if (kt == 0)
                o[rowbase + (size_t)t*CC + vg] = sd + sa*brs[t] + vt*krs[t];

            float4 d40 = *(const float4*)&shd[koff];
            float4 d41 = *(const float4*)&shd[koff+4];
            float4 b40 = *(const float4*)&shb[koff];
            float4 b41 = *(const float4*)&shb[koff+4];
            float4 k40 = *(const float4*)&shk[koff];
            float4 k41 = *(const float4*)&shk[koff+4];
            S[0] = S[0]*d40.x + sa*b40.x + vt*k40.x;
            S[1] = S[1]*d40.y + sa*b40.y + vt*k40.y;
            S[2] = S[2]*d40.z + sa*b40.z + vt*k40.z;
            S[3] = S[3]*d40.w + sa*b40.w + vt*k40.w;
            S[4] = S[4]*d41.x + sa*b41.x + vt*k41.x;
            S[5] = S[5]*d41.y + sa*b41.y + vt*k41.y;
            S[6] = S[6]*d41.z + sa*b41.z + vt*k41.z;
            S[7] = S[7]*d41.w + sa*b41.w + vt*k41.w;
        }
    }
}

// ---------------------------------------------------------------------------
// K7: group norm + per-head bonus + gate multiply -> bf16 hi/lo
// ---------------------------------------------------------------------------
__global__ __launch_bounds__(256) void gn_kernel(
    const float* __restrict__ o, const float* __restrict__ r,
    const float* __restrict__ kf, const float* __restrict__ vf,
    const float* __restrict__ gg, const float* __restrict__ rk,
    const float* __restrict__ gnw, const float* __restrict__ gnb,
    __nv_bfloat16* __restrict__ xoh, __nv_bfloat16* __restrict__ xol)
{
    const int tid = threadIdx.x;
    const int g = tid >> 6, n = tid & 63;
    const size_t head = (size_t)blockIdx.x*4 + g;
    const int h = (int)(head & (HH-1));
    const size_t idx = head*64 + n;
    const int c = h*64 + n;

    float ov = o[idx];
    float rv = r[idx], kv = kf[idx];
    float s1 = ov, s2 = ov*ov, s3 = rv*kv*rk[c];
#pragma unroll
    for (int off=16; off; off>>=1){
        s1 += __shfl_xor_sync(0xffffffffu, s1, off);
        s2 += __shfl_xor_sync(0xffffffffu, s2, off);
        s3 += __shfl_xor_sync(0xffffffffu, s3, off);
    }
    __shared__ float red[8][3];
    if ((tid & 31)==0){ int w = tid>>5; red[w][0]=s1; red[w][1]=s2; red[w][2]=s3; }
    __syncthreads();
    float S1 = red[g*2][0]+red[g*2+1][0];
    float S2 = red[g*2][1]+red[g*2+1][1];
    float S3 = red[g*2][2]+red[g*2+1][2];
    float mu = S1*(1.f/64.f);
    float var = S2*(1.f/64.f) - mu*mu;
    float y = (ov-mu)*rsqrtf(var + 6.4e-4f)*gnw[c] + gnb[c] + S3*vf[idx];
    float xo = y * gg[idx];
    __nv_bfloat16 hv, lv;
    split_hilo(xo, hv, lv);
    xoh[idx] = hv;
    xol[idx] = lv;
}

// ---------------------------------------------------------------------------
// Launch
// ---------------------------------------------------------------------------
extern "C" void kernel_launch(void* const* d_in, const int* in_sizes, int n_in,
                              void* d_out, int out_size)
{
    const float* h      = (const float*)d_in[0];
    const float* shift  = (const float*)d_in[1];
    const float* s0     = (const float*)d_in[2];
    const float* vfirst = (const float*)d_in[3];
    const float* x_r = (const float*)d_in[4];
    const float* x_w = (const float*)d_in[5];
    const float* x_k = (const float*)d_in[6];
    const float* x_v = (const float*)d_in[7];
    const float* x_a = (const float*)d_in[8];
    const float* x_g = (const float*)d_in[9];
    const float* w0 = (const float*)d_in[10];
    const float* w1 = (const float*)d_in[11];
    const float* w2 = (const float*)d_in[12];
    const float* a0 = (const float*)d_in[13];
    const float* a1 = (const float*)d_in[14];
    const float* a2 = (const float*)d_in[15];
    const float* v0 = (const float*)d_in[16];
    const float* v1 = (const float*)d_in[17];
    const float* v2 = (const float*)d_in[18];
    const float* g1 = (const float*)d_in[19];
    const float* g2 = (const float*)d_in[20];
    const float* k_k = (const float*)d_in[21];
    const float* k_a = (const float*)d_in[22];
    const float* r_k = (const float*)d_in[23];
    const float* W_r = (const float*)d_in[24];
    const float* W_k = (const float*)d_in[25];
    const float* W_v = (const float*)d_in[26];
    const float* W_o = (const float*)d_in[27];
    const float* gnw = (const float*)d_in[28];
    const float* gnb = (const float*)d_in[29];
    float* out = (float*)d_out;

    float* S = nullptr;
    cudaGetSymbolAddress((void**)&S, g_scratch);

    float* xw    = S + (size_t)S_XW*BTC;
    float* xa    = S + (size_t)S_XA*BTC;
    float* xv    = S + (size_t)S_XV*BTC;
    float* xg    = S + (size_t)S_XG*BTC;
    float* rb    = S + (size_t)S_R*BTC;
    float* kb    = S + (size_t)S_K*BTC;
    float* vb    = S + (size_t)S_V*BTC;
    float* decay = S + (size_t)S_DECAY*BTC;
    float* asig  = S + (size_t)S_ASIG*BTC;
    float* gbuf  = S + (size_t)S_G*BTC;
    float* awb   = S + (size_t)S_AW*BTC;
    float* bwb   = S + (size_t)S_BW*BTC;
    float* kfb   = S + (size_t)S_KF*BTC;
    float* vfb   = S + (size_t)S_VF*BTC;
    float* ob    = S + (size_t)S_O*BTC;
    float* drb   = S + (size_t)S_DR*BTC;

    __nv_bfloat16* bfb = (__nv_bfloat16*)(S + BF16_BASE);
#define BF(i) (bfb + (size_t)(i)*BTC)
    __nv_bfloat16 *xrh=BF(B_XRH), *xrl=BF(B_XRL), *xkh=BF(B_XKH), *xkl=BF(B_XKL);
    __nv_bfloat16 *xvh=BF(B_XVH), *xvl=BF(B_XVL), *xoh=BF(B_XOH), *xol=BF(B_XOL);
    __nv_bfloat16 *wrh=BF(B_WRH), *wrl=BF(B_WRL), *wkh=BF(B_WKH), *wkl=BF(B_WKL);
    __nv_bfloat16 *wvh=BF(B_WVH), *wvl=BF(B_WVL), *woh=BF(B_WOH), *wol=BF(B_WOL);
#undef BF
    __nv_bfloat16* ub = (__nv_bfloat16*)(S + U_OFF);
    __nv_bfloat16 *uwh = ub,                     *uwl = uwh + (size_t)BT*64;
    __nv_bfloat16 *uah = uwl + (size_t)BT*64,    *ual = uah + (size_t)BT*64;
    __nv_bfloat16 *uvh = ual + (size_t)BT*64,    *uvl = uvh + (size_t)BT*32;
    __nv_bfloat16 *ugh = uvl + (size_t)BT*32,    *ugl = ugh + (size_t)BT*128;
    __nv_bfloat16* vtb = (__nv_bfloat16*)(S + V2T_OFF);
    __nv_bfloat16 *w2h = vtb,                    *w2l = w2h + (size_t)CC*64;
    __nv_bfloat16 *a2h = w2l + (size_t)CC*64,    *a2l = a2h + (size_t)CC*64;
    __nv_bfloat16 *v2h = a2l + (size_t)CC*64,    *v2l = v2h + (size_t)CC*32;
    __nv_bfloat16 *g2h = v2l + (size_t)CC*32,    *g2l = g2h + (size_t)CC*128;

    float* brg = S + BR_OFF;  float* krg = S + KR_OFF;

    cudaFuncSetAttribute(gemm_lora_kernel,
                         cudaFuncAttributeMaxDynamicSharedMemorySize, GEMM_SMEM);
    cudaFuncSetAttribute(stage2_hmma,
                         cudaFuncAttributeMaxDynamicSharedMemorySize, GEMM_SMEM);

    // 0a. big weight conversions
    CvtJobs cj;
    cj.x[0]=W_r; cj.hi[0]=wrh; cj.lo[0]=wrl;
    cj.x[1]=W_k; cj.hi[1]=wkh; cj.lo[1]=wkl;
    cj.x[2]=W_v; cj.hi[2]=wvh; cj.lo[2]=wvl;
    cj.x[3]=W_o; cj.hi[3]=woh; cj.lo[3]=wol;
    cvt_all_kernel<<<dim3(4096, 4), 256>>>(cj);

    // 0b. V2 transpose + hi/lo
    V2tJobs vj;
    vj.src[0]=w2; vj.dh[0]=w2h; vj.dl[0]=w2l; vj.D[0]=64;
    vj.src[1]=a2; vj.dh[1]=a2h; vj.dl[1]=a2l; vj.D[1]=64;
    vj.src[2]=v2; vj.dh[2]=v2h; vj.dl[2]=v2l; vj.D[2]=32;
    vj.src[3]=g2; vj.dh[3]=g2h; vj.dl[3]=g2l; vj.D[3]=128;
    cvt_v2t_kernel<<<dim3(1024, 4), 256>>>(vj);

    // 1. token shift + mixes
    mix_kernel<<<4096, 256>>>(h, shift, x_r, x_w, x_k, x_v, x_a, x_g,
                              xrh, xrl, xw, xkh, xkl, xv, xvh, xvl, xa, xg);

    // 2+3. FUSED: r/k/v projections + LoRA stage 1 (act applied pre-split)
    FusedJobs fj;
    fj.g[0] = { xrh, xrl, wrh, wrl, rb };
    fj.g[1] = { xkh, xkl, wkh, wkl, kb };
    fj.g[2] = { xvh, xvl, wvh, wvl, vb };
    fj.l[0] = { xw, w1, uwh, uwl,  64, 0, 1 };   // tanh
    fj.l[1] = { xa, a1, uah, ual,  64, 0, 0 };
    fj.l[2] = { xv, v1, uvh, uvl,  32, 0, 0 };
    fj.l[3] = { xg, g1, ugh, ugl, 128, 0, 2 };   // sigmoid
    fj.l[4] = { xg, g1, ugh, ugl, 128, 64, 2 };  // sigmoid
    gemm_lora_kernel<<<dim3(8, 16, 5), 256, GEMM_SMEM>>>(fj, 3);

    // 4. LoRA stage 2 on HMMA + fused epilogues
    S2Jobs sj;
    sj.j[0] = { uwh, uwl, w2h, w2l, w0, decay, nullptr, nullptr,  64, 0 };
    sj.j[1] = { uah, ual, a2h, a2l, a0, asig,  nullptr, nullptr,  64, 1 };
    sj.j[2] = { uvh, uvl, v2h, v2l, v0, vfb,   vb,      vfirst,   32, 2 };
    sj.j[3] = { ugh, ugl, g2h, g2l, nullptr, gbuf, nullptr, nullptr, 128, 3 };
    stage2_hmma<<<dim3(8, 16, 4), 256, GEMM_SMEM>>>(sj);

    // 5. prep + per-step scalars + dr
    prep_kernel<<<BT*HH/4, 256>>>(kb, rb, asig, decay, k_k, k_a,
                                  awb, bwb, kfb, drb, brg, krg);

    // 6. WKV7 recurrence (pair-step ring)
    wkv_kernel<<<BB*HH*4, 128>>>(drb, kfb, vfb, decay, awb, bwb, brg, krg, s0, ob);

    // 7. group norm + bonus + gate
    gn_kernel<<<BT*HH/4, 256>>>(ob, rb, kfb, vfb, gbuf, r_k, gnw, gnb, xoh, xol);

    // 8. output projection
    FusedJobs oj = fj;
    oj.g[0] = { xoh, xol, woh, wol, out };
    gemm_lora_kernel<<<dim3(8, 16, 1), 256, GEMM_SMEM>>>(oj, 1);
}

// round 11
// speedup vs baseline: 1.3389x; 1.0125x over previous
#include <cuda_runtime.h>
#include <cuda_bf16.h>
#include <math.h>
#include <cstdint>

// Problem constants
#define BB 2
#define TT 1024
#define CC 2048
#define HH 32
#define NN 64
#define BT (BB*TT)              // 2048
#define BTC (BB*TT*CC)          // 4194304  (== CC*CC)

// ---------------------------------------------------------------------------
// Scratch (static device memory)
// ---------------------------------------------------------------------------
enum { S_XW=0, S_XA, S_XV, S_XG, S_R, S_K, S_V,
       S_DECAY, S_ASIG, S_G, S_AW, S_BW, S_KF, S_VF, S_O, S_DR, N_F32 };
enum { B_XRH=0, B_XRL, B_XKH, B_XKL, B_XVH, B_XVL, B_XOH, B_XOL,
       B_WRH, B_WRL, B_WKH, B_WKL, B_WVH, B_WVL, B_WOH, B_WOL, N_BF16 };
#define BF16_BASE ((size_t)N_F32*BTC)                 // in floats
#define U_OFF     (BF16_BASE + (size_t)N_BF16*BTC/2)  // bf16 U region
#define BR_OFF    (U_OFF + (size_t)BT*288)
#define KR_OFF    (BR_OFF + (size_t)BB*HH*TT)
#define V2T_OFF   (KR_OFF + (size_t)BB*HH*TT)         // bf16 V2T region
#define SCRATCH_FLOATS (V2T_OFF + (size_t)CC*288 + 256)

__device__ float g_scratch[SCRATCH_FLOATS];

// ---------------------------------------------------------------------------
// PTX helpers
// ---------------------------------------------------------------------------
__device__ __forceinline__ uint32_t smem_u32(const void* p) {
    uint32_t a;
    asm("{ .reg .u64 t; cvta.to.shared.u64 t, %1; cvt.u32.u64 %0, t; }" : "=r"(a) : "l"(p));
    return a;
}
#define CP16(dst, src) \
    asm volatile("cp.async.cg.shared.global [%0], [%1], 16;" :: "r"(dst), "l"(src))
#define CP_COMMIT() asm volatile("cp.async.commit_group;" ::: "memory")
#define LDSM4(r, addr) \
    asm volatile("ldmatrix.sync.aligned.m8n8.x4.shared.b16 {%0,%1,%2,%3}, [%4];" \
        : "=r"((r)[0]), "=r"((r)[1]), "=r"((r)[2]), "=r"((r)[3]) : "r"(addr))
#define MMA16816(d, a, b0, b1) \
    asm volatile("mma.sync.aligned.m16n8k16.row.col.f32.bf16.bf16.f32 " \
        "{%0,%1,%2,%3}, {%4,%5,%6,%7}, {%8,%9}, {%0,%1,%2,%3};" \
        : "+f"((d)[0]), "+f"((d)[1]), "+f"((d)[2]), "+f"((d)[3]) \
        : "r"((a)[0]), "r"((a)[1]), "r"((a)[2]), "r"((a)[3]), "r"(b0), "r"(b1))

__device__ __forceinline__ void split_hilo(float v, __nv_bfloat16& h, __nv_bfloat16& l) {
    h = __float2bfloat16(v);
    l = __float2bfloat16(v - __bfloat162float(h));
}
__device__ __forceinline__ void store_hilo4(__nv_bfloat16* hi, __nv_bfloat16* lo,
                                            size_t off, float4 v) {
    __nv_bfloat16 hv[4], lv[4];
    split_hilo(v.x, hv[0], lv[0]); split_hilo(v.y, hv[1], lv[1]);
    split_hilo(v.z, hv[2], lv[2]); split_hilo(v.w, hv[3], lv[3]);
    *(uint2*)&hi[off] = *(uint2*)hv;
    *(uint2*)&lo[off] = *(uint2*)lv;
}

// ---------------------------------------------------------------------------
// K0a: batched fp32 -> bf16 hi/lo conversion (4 big weights)
// ---------------------------------------------------------------------------
struct CvtJobs { const float* x[4]; __nv_bfloat16* hi[4]; __nv_bfloat16* lo[4]; };

__global__ __launch_bounds__(256) void cvt_all_kernel(CvtJobs jobs)
{
    const int z = blockIdx.y;
    size_t i = ((size_t)blockIdx.x * 256 + threadIdx.x) * 4;
    float4 v = *(const float4*)&jobs.x[z][i];
    store_hilo4(jobs.hi[z], jobs.lo[z], i, v);
}

// ---------------------------------------------------------------------------
// K0b: V2 transpose + hi/lo: src [D, CC] fp32 -> dst [CC, D] bf16 hi/lo
// ---------------------------------------------------------------------------
struct V2tJobs { const float* src[4]; __nv_bfloat16* dh[4]; __nv_bfloat16* dl[4]; int D[4]; };

__global__ __launch_bounds__(256) void cvt_v2t_kernel(V2tJobs jobs)
{
    const int z = blockIdx.y;
    const int D = jobs.D[z];
    int i = blockIdx.x * 256 + threadIdx.x;
    if (i >= CC * D) return;
    int c = i / D, d = i - c * D;
    float v = jobs.src[z][(size_t)d * CC + c];
    __nv_bfloat16 h, l;
    split_hilo(v, h, l);
    jobs.dh[z][i] = h;
    jobs.dl[z][i] = l;
}

// ---------------------------------------------------------------------------
// K1: token shift + 6-way mix
// ---------------------------------------------------------------------------
__global__ __launch_bounds__(256) void mix_kernel(
    const float* __restrict__ h, const float* __restrict__ shift,
    const float* __restrict__ mr, const float* __restrict__ mw,
    const float* __restrict__ mk, const float* __restrict__ mv,
    const float* __restrict__ ma, const float* __restrict__ mg,
    __nv_bfloat16* __restrict__ xrh, __nv_bfloat16* __restrict__ xrl,
    float* __restrict__ oxw,
    __nv_bfloat16* __restrict__ xkh, __nv_bfloat16* __restrict__ xkl,
    float* __restrict__ oxv,
    __nv_bfloat16* __restrict__ xvh, __nv_bfloat16* __restrict__ xvl,
    float* __restrict__ oxa, float* __restrict__ oxg)
{
    int gid = blockIdx.x * 256 + threadIdx.x;
    int row = gid >> 9;
    int c   = (gid & 511) << 2;
    int t   = row & (TT-1);
    int b   = row >> 10;
    size_t off = (size_t)row * CC + c;

    float4 hv = *(const float4*)&h[off];
    float4 pv;
    if (t == 0) pv = *(const float4*)&shift[(size_t)b*CC + c];
    else        pv = *(const float4*)&h[off - CC];
    float4 xx = make_float4(pv.x-hv.x, pv.y-hv.y, pv.z-hv.z, pv.w-hv.w);

#define MIXV(mvec, o)                                                 \
    {   float4 m = *(const float4*)&mvec[c];                          \
        o = make_float4(hv.x + xx.x*m.x, hv.y + xx.y*m.y,             \
                        hv.z + xx.z*m.z, hv.w + xx.w*m.w); }
    float4 vr; MIXV(mr, vr); store_hilo4(xrh, xrl, off, vr);
    float4 vw; MIXV(mw, vw); *(float4*)&oxw[off] = vw;
    float4 vk; MIXV(mk, vk); store_hilo4(xkh, xkl, off, vk);
    float4 vv; MIXV(mv, vv); *(float4*)&oxv[off] = vv; store_hilo4(xvh, xvl, off, vv);
    float4 va; MIXV(ma, va); *(float4*)&oxa[off] = va;
    float4 vg; MIXV(mg, vg); *(float4*)&oxg[off] = vg;
#undef MIXV
}

// ---------------------------------------------------------------------------
// K2: FUSED HMMA bf16x3 GEMM + LoRA stage 1.
//     4-stage ring, prefetch distance 3, ONE barrier per K-iteration.
// ---------------------------------------------------------------------------
#define GSTAGES 4
#define TILE_A 8192
#define TILE_B 16384
#define STAGE_B (2*TILE_A + 2*TILE_B)    // 49152
#define GEMM_SMEM (GSTAGES*STAGE_B)      // 196608

struct GemmJob  { const __nv_bfloat16 *Ah, *Al, *Bh, *Bl; float* Y; };
struct Lora1Job { const float* X; const float* G;
                  __nv_bfloat16* Uh; __nv_bfloat16* Ul; int D; int col0; int act; };
struct FusedJobs { GemmJob g[3]; Lora1Job l[5]; };

__device__ __forceinline__ uint32_t swz(uint32_t row, uint32_t chunk) {
    return row*64u + ((chunk ^ ((row >> 1) & 3u)) << 4);
}

__device__ void gemm_path(const GemmJob& gj, char* dynsmem)
{
    const __nv_bfloat16* __restrict__ Ahi = gj.Ah;
    const __nv_bfloat16* __restrict__ Alo = gj.Al;
    const __nv_bfloat16* __restrict__ Bhi = gj.Bh;
    const __nv_bfloat16* __restrict__ Blo = gj.Bl;
    float* __restrict__ Y = gj.Y;

    const uint32_t sb = smem_u32(dynsmem);
    const int tid  = threadIdx.x;
    const int lane = tid & 31;
    const int warp = tid >> 5;
    const int wm = warp >> 2;
    const int wn = warp & 3;
    const int bm = blockIdx.y << 7;
    const int bn = blockIdx.x << 8;

    auto load_stage = [&](int chunk, int stage) {
        const uint32_t st = sb + (uint32_t)stage * STAGE_B;
        const int k0 = chunk << 5;
#pragma unroll
        for (int i = 0; i < 2; i++) {
            int idx = tid + (i << 8);
            int row = idx >> 2, ch = idx & 3;
            uint32_t d = st + swz(row, ch);
            size_t g = (size_t)(bm + row) * CC + k0 + ch * 8;
            CP16(d,          Ahi + g);
            CP16(d + TILE_A, Alo + g);
        }
#pragma unroll
        for (int i = 0; i < 4; i++) {
            int idx = tid + (i << 8);
            int row = idx >> 2, ch = idx & 3;
            uint32_t d = st + 2*TILE_A + swz(row, ch);
            size_t g = (size_t)(bn + row) * CC + k0 + ch * 8;
            CP16(d,          Bhi + g);
            CP16(d + TILE_B, Blo + g);
        }
    };

    float acc[4][8][4];
#pragma unroll
    for (int mi=0;mi<4;mi++)
#pragma unroll
        for (int ni=0;ni<8;ni++)
#pragma unroll
            for (int j=0;j<4;j++) acc[mi][ni][j] = 0.f;

#pragma unroll
    for (int s = 0; s < 3; s++) { load_stage(s, s); CP_COMMIT(); }

    const int a_row = wm*64 + (lane & 7) + ((lane >> 3) & 1) * 8;
    const int a_ch  = (lane >> 4);
    const int b_row = wn*64 + (lane & 7) + (lane >> 4) * 8;
    const int b_ch  = ((lane >> 3) & 1);

    for (int it = 0; it < 64; it++) {
        const uint32_t st = sb + (uint32_t)(it & 3) * STAGE_B;
        asm volatile("cp.async.wait_group 2;" ::: "memory");
        __syncthreads();
        if (it + 3 < 64) load_stage(it + 3, (it + 3) & 3);
        CP_COMMIT();

#pragma unroll
        for (int ks = 0; ks < 2; ks++) {
            uint32_t ah[4][4], al[4][4], b[4][4];
#pragma unroll
            for (int mi = 0; mi < 4; mi++) {
                uint32_t a = st + swz((uint32_t)(a_row + mi*16), (uint32_t)(a_ch + ks*2));
                LDSM4(ah[mi], a);
                LDSM4(al[mi], a + TILE_A);
            }
#pragma unroll
            for (int j = 0; j < 4; j++) {
                uint32_t baddr = st + 2*TILE_A +
                    swz((uint32_t)(b_row + j*16), (uint32_t)(b_ch + ks*2));
                LDSM4(b[j], baddr);
            }
#pragma unroll
            for (int mi = 0; mi < 4; mi++)
#pragma unroll
                for (int ni = 0; ni < 8; ni++)
                    MMA16816(acc[mi][ni], ah[mi], b[ni>>1][(ni&1)*2], b[ni>>1][(ni&1)*2+1]);
#pragma unroll
            for (int mi = 0; mi < 4; mi++)
#pragma unroll
                for (int ni = 0; ni < 8; ni++)
                    MMA16816(acc[mi][ni], al[mi], b[ni>>1][(ni&1)*2], b[ni>>1][(ni&1)*2+1]);
#pragma unroll
            for (int j = 0; j < 4; j++) {
                uint32_t baddr = st + 2*TILE_A + TILE_B +
                    swz((uint32_t)(b_row + j*16), (uint32_t)(b_ch + ks*2));
                LDSM4(b[j], baddr);
            }
#pragma unroll
            for (int mi = 0; mi < 4; mi++)
#pragma unroll
                for (int ni = 0; ni < 8; ni++)
                    MMA16816(acc[mi][ni], ah[mi], b[ni>>1][(ni&1)*2], b[ni>>1][(ni&1)*2+1]);
        }
    }

    const int erow = bm + wm*64 + (lane >> 2);
    const int ecol = bn + wn*64 + (lane & 3) * 2;
#pragma unroll
    for (int mi = 0; mi < 4; mi++)
#pragma unroll
        for (int ni = 0; ni < 8; ni++) {
            size_t r0 = (size_t)(erow + mi*16) * CC + ecol + ni*8;
            *(float2*)&Y[r0]        = make_float2(acc[mi][ni][0], acc[mi][ni][1]);
            *(float2*)&Y[r0 + 8*CC] = make_float2(acc[mi][ni][2], acc[mi][ni][3]);
        }
}

__device__ void lora_path(const Lora1Job& jb, int mblk, char* dynsmem)
{
    const float* __restrict__ X = jb.X;
    const float* __restrict__ G = jb.G;
    const int D = jb.D, col0 = jb.col0, act = jb.act;

    float* Xs = (float*)dynsmem;            // [32][68]
    float* Gs = Xs + 32*68;                 // [32][64]

    const int tid = threadIdx.x;
    const int bm = mblk * 64;
    const int tx = tid & 15;
    const int ty = tid >> 4;

    float4 px[2], pg[2];
    const int xrow = tid & 63;
    const int xkc0 = (tid >> 6) << 2;
    const int gkr0 = tid >> 4;
    const int gcc  = (tid & 15) << 2;

    auto gload = [&](int k0) {
#pragma unroll
        for (int i = 0; i < 2; i++) {
            px[i] = *(const float4*)&X[(size_t)(bm + xrow)*CC + k0 + xkc0 + i*16];
            if (col0 + gcc < D)
                pg[i] = *(const float4*)&G[(size_t)(k0 + gkr0 + i*16)*D + col0 + gcc];
            else
                pg[i] = make_float4(0.f, 0.f, 0.f, 0.f);
        }
    };
    auto sstore = [&]() {
#pragma unroll
        for (int i = 0; i < 2; i++) {
            int kc = xkc0 + i*16;
            Xs[(kc+0)*68+xrow] = px[i].x; Xs[(kc+1)*68+xrow] = px[i].y;
            Xs[(kc+2)*68+xrow] = px[i].z; Xs[(kc+3)*68+xrow] = px[i].w;
            *(float4*)&Gs[(gkr0 + i*16)*64 + gcc] = pg[i];
        }
    };

    float acc[4][4];
#pragma unroll
    for (int i=0;i<4;i++)
#pragma unroll
        for (int j=0;j<4;j++) acc[i][j] = 0.f;

    gload(0); sstore(); __syncthreads();

    for (int k0 = 32; k0 <= 2048; k0 += 32) {
        if (k0 < 2048) gload(k0);
#pragma unroll
        for (int kk = 0; kk < 32; kk++) {
            float4 xa = *(const float4*)&Xs[kk*68 + ty*4];
            float4 gb = *(const float4*)&Gs[kk*64 + tx*4];
            float xv[4] = {xa.x, xa.y, xa.z, xa.w};
            float gv[4] = {gb.x, gb.y, gb.z, gb.w};
#pragma unroll
            for (int i=0;i<4;i++)
#pragma unroll
                for (int j=0;j<4;j++)
                    acc[i][j] += xv[i]*gv[j];
        }
        __syncthreads();
        if (k0 < 2048) { sstore(); __syncthreads(); }
    }

#pragma unroll
    for (int i=0;i<4;i++) {
        int row = bm + ty*4 + i;
#pragma unroll
        for (int j=0;j<4;j++) {
            int col = col0 + tx*4 + j;
            if (col < D) {
                float y = acc[i][j];
                if (act == 1) y = tanhf(y);
                else if (act == 2) y = 1.f/(1.f+expf(-y));
                __nv_bfloat16 hv, lv;
                split_hilo(y, hv, lv);
                jb.Uh[(size_t)row*D + col] = hv;
                jb.Ul[(size_t)row*D + col] = lv;
            }
        }
    }
}

__global__ __launch_bounds__(256, 1) void gemm_lora_kernel(FusedJobs jobs, int nz_gemm)
{
    extern __shared__ char dynsmem[];
    const int z = blockIdx.z;
    if (z < nz_gemm) {
        gemm_path(jobs.g[z], dynsmem);
    } else {
        int lin = (z - nz_gemm)*128 + blockIdx.y*8 + blockIdx.x;
        if (lin >= 160) return;
        lora_path(jobs.l[lin >> 5], lin & 31, dynsmem);
    }
}

// ---------------------------------------------------------------------------
// K4: stage2 on HMMA (4-stage ring, single barrier per iteration)
// ---------------------------------------------------------------------------
struct S2Job  { const __nv_bfloat16 *Ah, *Al, *Bh, *Bl; const float* bias;
                float* out; const float* e1; const float* e2; int D; int mode; };
struct S2Jobs { S2Job j[4]; };

__global__ __launch_bounds__(256, 1) void stage2_hmma(S2Jobs jobs)
{
    extern __shared__ char dynsmem[];
    const S2Job jb = jobs.j[blockIdx.z];
    const int D = jb.D, nk = D >> 5, mode = jb.mode;

    const uint32_t sb = smem_u32(dynsmem);
    const int tid  = threadIdx.x;
    const int lane = tid & 31;
    const int warp = tid >> 5;
    const int wm = warp >> 2;
    const int wn = warp & 3;
    const int bm = blockIdx.y << 7;
    const int bn = blockIdx.x << 8;

    auto load_stage = [&](int chunk, int stage) {
        const uint32_t st = sb + (uint32_t)stage * STAGE_B;
        const int k0 = chunk << 5;
#pragma unroll
        for (int i = 0; i < 2; i++) {
            int idx = tid + (i << 8);
            int row = idx >> 2, ch = idx & 3;
            uint32_t d = st + swz(row, ch);
            size_t g = (size_t)(bm + row) * D + k0 + ch * 8;
            CP16(d,          jb.Ah + g);
            CP16(d + TILE_A, jb.Al + g);
        }
#pragma unroll
        for (int i = 0; i < 4; i++) {
            int idx = tid + (i << 8);
            int row = idx >> 2, ch = idx & 3;
            uint32_t d = st + 2*TILE_A + swz(row, ch);
            size_t g = (size_t)(bn + row) * D + k0 + ch * 8;
            CP16(d,          jb.Bh + g);
            CP16(d + TILE_B, jb.Bl + g);
        }
    };

    float acc[4][8][4];
#pragma unroll
    for (int mi=0;mi<4;mi++)
#pragma unroll
        for (int ni=0;ni<8;ni++)
#pragma unroll
            for (int j=0;j<4;j++) acc[mi][ni][j] = 0.f;

#pragma unroll
    for (int s = 0; s < 3; s++) {
        if (s < nk) load_stage(s, s);
        CP_COMMIT();
    }

    const int a_row = wm*64 + (lane & 7) + ((lane >> 3) & 1) * 8;
    const int a_ch  = (lane >> 4);
    const int b_row = wn*64 + (lane & 7) + (lane >> 4) * 8;
    const int b_ch  = ((lane >> 3) & 1);

    for (int it = 0; it < nk; it++) {
        const uint32_t st = sb + (uint32_t)(it & 3) * STAGE_B;
        asm volatile("cp.async.wait_group 2;" ::: "memory");
        __syncthreads();
        if (it + 3 < nk) load_stage(it + 3, (it + 3) & 3);
        CP_COMMIT();

#pragma unroll
        for (int ks = 0; ks < 2; ks++) {
            uint32_t ah[4][4], al[4][4], b[4][4];
#pragma unroll
            for (int mi = 0; mi < 4; mi++) {
                uint32_t a = st + swz((uint32_t)(a_row + mi*16), (uint32_t)(a_ch + ks*2));
                LDSM4(ah[mi], a);
                LDSM4(al[mi], a + TILE_A);
            }
#pragma unroll
            for (int j = 0; j < 4; j++) {
                uint32_t baddr = st + 2*TILE_A +
                    swz((uint32_t)(b_row + j*16), (uint32_t)(b_ch + ks*2));
                LDSM4(b[j], baddr);
            }
#pragma unroll
            for (int mi = 0; mi < 4; mi++)
#pragma unroll
                for (int ni = 0; ni < 8; ni++)
                    MMA16816(acc[mi][ni], ah[mi], b[ni>>1][(ni&1)*2], b[ni>>1][(ni&1)*2+1]);
#pragma unroll
            for (int mi = 0; mi < 4; mi++)
#pragma unroll
                for (int ni = 0; ni < 8; ni++)
                    MMA16816(acc[mi][ni], al[mi], b[ni>>1][(ni&1)*2], b[ni>>1][(ni&1)*2+1]);
#pragma unroll
            for (int j = 0; j < 4; j++) {
                uint32_t baddr = st + 2*TILE_A + TILE_B +
                    swz((uint32_t)(b_row + j*16), (uint32_t)(b_ch + ks*2));
                LDSM4(b[j], baddr);
            }
#pragma unroll
            for (int mi = 0; mi < 4; mi++)
#pragma unroll
                for (int ni = 0; ni < 8; ni++)
                    MMA16816(acc[mi][ni], ah[mi], b[ni>>1][(ni&1)*2], b[ni>>1][(ni&1)*2+1]);
        }
    }

    const int erow = bm + wm*64 + (lane >> 2);
    const int ecol = bn + wn*64 + (lane & 3) * 2;
#pragma unroll
    for (int mi = 0; mi < 4; mi++)
#pragma unroll
        for (int ni = 0; ni < 8; ni++) {
            const int c = ecol + ni*8;
            size_t r0 = (size_t)(erow + mi*16) * CC + c;
            float2 p0 = make_float2(acc[mi][ni][0], acc[mi][ni][1]);
            float2 p1 = make_float2(acc[mi][ni][2], acc[mi][ni][3]);
            if (mode == 3) {
                *(float2*)&jb.out[r0]        = p0;
                *(float2*)&jb.out[r0 + 8*CC] = p1;
            } else {
                float b0 = jb.bias[c], b1 = jb.bias[c+1];
                float s00 = 1.f/(1.f+expf(-(p0.x+b0)));
                float s01 = 1.f/(1.f+expf(-(p0.y+b1)));
                float s10 = 1.f/(1.f+expf(-(p1.x+b0)));
                float s11 = 1.f/(1.f+expf(-(p1.y+b1)));
                if (mode == 0) {
                    const float e = 0.6065306597126334f;
                    *(float2*)&jb.out[r0]        = make_float2(e*s00, e*s01);
                    *(float2*)&jb.out[r0 + 8*CC] = make_float2(e*s10, e*s11);
                } else if (mode == 1) {
                    *(float2*)&jb.out[r0]        = make_float2(s00, s01);
                    *(float2*)&jb.out[r0 + 8*CC] = make_float2(s10, s11);
                } else {
                    float2 a0 = *(const float2*)&jb.e1[r0];
                    float2 f0 = *(const float2*)&jb.e2[r0];
                    float2 a1 = *(const float2*)&jb.e1[r0 + 8*CC];
                    float2 f1 = *(const float2*)&jb.e2[r0 + 8*CC];
                    *(float2*)&jb.out[r0] =
                        make_float2(a0.x + (f0.x-a0.x)*s00, a0.y + (f0.y-a0.y)*s01);
                    *(float2*)&jb.out[r0 + 8*CC] =
                        make_float2(a1.x + (f1.x-a1.x)*s10, a1.y + (f1.y-a1.y)*s11);
                }
            }
        }
}

// ---------------------------------------------------------------------------
// K5: per-(b,t,h) prep + per-step scalars + dr = decay*r
// ---------------------------------------------------------------------------
__global__ __launch_bounds__(256) void prep_kernel(
    const float* __restrict__ k, const float* __restrict__ r,
    const float* __restrict__ asig, const float* __restrict__ decay,
    const float* __restrict__ kkvec, const float* __restrict__ kavec,
    float* __restrict__ aw, float* __restrict__ bw, float* __restrict__ kf,
    float* __restrict__ drb,
    float* __restrict__ brg, float* __restrict__ krg)
{
    const int tid = threadIdx.x;
    const int g = tid >> 6, n = tid & 63;
    const size_t head = (size_t)blockIdx.x*4 + g;
    const size_t idx = head*64 + n;
    const int c = (int)(idx & (CC-1));

    float kv = k[idx];
    float kk = kv * kkvec[c];
    float ss = kk*kk;
#pragma unroll
    for (int off=16; off; off>>=1) ss += __shfl_xor_sync(0xffffffffu, ss, off);
    __shared__ float red[8];
    if ((tid & 31)==0) red[tid>>5] = ss;
    __syncthreads();
    float tot = red[g*2] + red[g*2+1];
    float inv = 1.f / fmaxf(sqrtf(tot), 1e-12f);
    float kkn = kk * inv;
    float a = asig[idx];
    float awv = -kkn;
    float bwv = kkn * a;
    float kfv = kv + kavec[c]*(kv*a - kv);
    aw[idx] = awv;
    bw[idx] = bwv;
    kf[idx] = kfv;

    float rv = r[idx];
    drb[idx] = decay[idx] * rv;

    float s1 = bwv*rv, s2 = kfv*rv;
#pragma unroll
    for (int off=16; off; off>>=1){
        s1 += __shfl_xor_sync(0xffffffffu, s1, off);
        s2 += __shfl_xor_sync(0xffffffffu, s2, off);
    }
    __shared__ float red2[8][2];
    if ((tid & 31)==0){ int w = tid>>5; red2[w][0]=s1; red2[w][1]=s2; }
    __syncthreads();
    if (n == 0) {
        float BR = red2[g*2][0] + red2[g*2+1][0];
        float KR = red2[g*2][1] + red2[g*2+1][1];
        int row = (int)(head >> 5);
        int hh  = (int)(head & 31);
        int bb  = row >> 10, t = row & (TT-1);
        size_t off2 = ((size_t)bb*HH + hh)*TT + t;
        brg[off2] = BR;
        krg[off2] = KR;
    }
}

// ---------------------------------------------------------------------------
// K6: WKV7 recurrence — round-9 known-good PF-6 single-step cp.async ring.
// ---------------------------------------------------------------------------
#define PF 6

__global__ __launch_bounds__(128) void wkv_kernel(
    const float* __restrict__ dr, const float* __restrict__ k,
    const float* __restrict__ v, const float* __restrict__ d,
    const float* __restrict__ aw, const float* __restrict__ bw,
    const float* __restrict__ brg, const float* __restrict__ krg,
    const float* __restrict__ s0, float* __restrict__ o)
{
    const int blk = blockIdx.x;
    const int bh = blk >> 2;
    const int vq = blk & 3;
    const int b = bh >> 5, hh = bh & 31;
    const int tid = threadIdx.x;
    const int vr = tid >> 3;
    const int kt = tid & 7;
    const int koff = kt * 8;
    const int vg = vq*16 + vr;

    __shared__ float ring[PF][6][64];
    __shared__ float brs[TT], krs[TT];

    const size_t rowbase = (size_t)b*TT*CC + hh*64;
    const uint32_t ring0 = smem_u32(ring);

    const float* src16 = nullptr;
    uint32_t doff16 = 0;
    if (tid < 96) {
        int arr = tid >> 4, c4 = tid & 15;
        const float* bp = (arr==0) ? dr : (arr==1) ? k : (arr==2) ? v :
                          (arr==3) ? d : (arr==4) ? aw : bw;
        src16 = bp + rowbase + c4*4;
        doff16 = (uint32_t)((arr*64 + c4*4) * 4);
    }

    {
        const float* brp = brg + ((size_t)b*HH + hh)*TT;
        const float* krp = krg + ((size_t)b*HH + hh)*TT;
        for (int i = tid; i < TT; i += 128) { brs[i] = brp[i]; krs[i] = krp[i]; }
    }

    float S[8];
    {
        const float* sp = s0 + ((size_t)bh*64 + vg)*64 + koff;
#pragma unroll
        for (int i=0;i<8;i++) S[i] = sp[i];
    }

#pragma unroll
    for (int s = 0; s < PF-1; s++) {
        if (tid < 96)
            CP16(ring0 + (uint32_t)s*(6*64*4) + doff16, src16 + (size_t)s*CC);
        CP_COMMIT();
    }

    int buf = 0;
    for (int t = 0; t < TT; t++) {
        asm volatile("cp.async.wait_group %0;" :: "n"(PF-2) : "memory");
        __syncthreads();

        {
            const int ts = t + PF - 1;
            int pbuf = buf - 1; if (pbuf < 0) pbuf += PF;
            if (ts < TT && tid < 96)
                CP16(ring0 + (uint32_t)pbuf*(6*64*4) + doff16, src16 + (size_t)ts*CC);
            CP_COMMIT();
        }

        const float* shdr = ring[buf][0];
        const float* shk  = ring[buf][1];
        const float* shv  = ring[buf][2];
        const float* shd  = ring[buf][3];
        const float* sha  = ring[buf][4];
        const float* shb  = ring[buf][5];

        float4 a40 = *(const float4*)&sha[koff];
        float4 a41 = *(const float4*)&sha[koff+4];
        float4 g40 = *(const float4*)&shdr[koff];
        float4 g41 = *(const float4*)&shdr[koff+4];

        float sa0, sa1, sd0, sd1;
        sa0 = S[0]*a40.x;           sa1 = S[1]*a40.y;
        sa0 += S[2]*a40.z;          sa1 += S[3]*a40.w;
        sa0 += S[4]*a41.x;          sa1 += S[5]*a41.y;
        sa0 += S[6]*a41.z;          sa1 += S[7]*a41.w;
        sd0 = S[0]*g40.x;           sd1 = S[1]*g40.y;
        sd0 += S[2]*g40.z;          sd1 += S[3]*g40.w;
        sd0 += S[4]*g41.x;          sd1 += S[5]*g41.y;
        sd0 += S[6]*g41.z;          sd1 += S[7]*g41.w;
        float sa = sa0 + sa1;
        float sd = sd0 + sd1;
        sa += __shfl_xor_sync(0xffffffffu, sa, 1);
        sd += __shfl_xor_sync(0xffffffffu, sd, 1);
        sa += __shfl_xor_sync(0xffffffffu, sa, 2);
        sd += __shfl_xor_sync(0xffffffffu, sd, 2);
        sa += __shfl_xor_sync(0xffffffffu, sa, 4);
        sd += __shfl_xor_sync(0xffffffffu, sd, 4);

        const float vt = shv[vg];
        if (kt == 0)
            o[rowbase + (size_t)t*CC + vg] = sd + sa*brs[t] + vt*krs[t];

        float4 d40 = *(const float4*)&shd[koff];
        float4 d41 = *(const float4*)&shd[koff+4];
        float4 b40 = *(const float4*)&shb[koff];
        float4 b41 = *(const float4*)&shb[koff+4];
        float4 k40 = *(const float4*)&shk[koff];
        float4 k41 = *(const float4*)&shk[koff+4];
        S[0] = S[0]*d40.x + sa*b40.x + vt*k40.x;
        S[1] = S[1]*d40.y + sa*b40.y + vt*k40.y;
        S[2] = S[2]*d40.z + sa*b40.z + vt*k40.z;
        S[3] = S[3]*d40.w + sa*b40.w + vt*k40.w;
        S[4] = S[4]*d41.x + sa*b41.x + vt*k41.x;
        S[5] = S[5]*d41.y + sa*b41.y + vt*k41.y;
        S[6] = S[6]*d41.z + sa*b41.z + vt*k41.z;
        S[7] = S[7]*d41.w + sa*b41.w + vt*k41.w;

        buf++; if (buf == PF) buf = 0;
    }
}

// ---------------------------------------------------------------------------
// K7: group norm + per-head bonus + gate multiply -> bf16 hi/lo
// ---------------------------------------------------------------------------
__global__ __launch_bounds__(256) void gn_kernel(
    const float* __restrict__ o, const float* __restrict__ r,
    const float* __restrict__ kf, const float* __restrict__ vf,
    const float* __restrict__ gg, const float* __restrict__ rk,
    const float* __restrict__ gnw, const float* __restrict__ gnb,
    __nv_bfloat16* __restrict__ xoh, __nv_bfloat16* __restrict__ xol)
{
    const int tid = threadIdx.x;
    const int g = tid >> 6, n = tid & 63;
    const size_t head = (size_t)blockIdx.x*4 + g;
    const int h = (int)(head & (HH-1));
    const size_t idx = head*64 + n;
    const int c = h*64 + n;

    float ov = o[idx];
    float rv = r[idx], kv = kf[idx];
    float s1 = ov, s2 = ov*ov, s3 = rv*kv*rk[c];
#pragma unroll
    for (int off=16; off; off>>=1){
        s1 += __shfl_xor_sync(0xffffffffu, s1, off);
        s2 += __shfl_xor_sync(0xffffffffu, s2, off);
        s3 += __shfl_xor_sync(0xffffffffu, s3, off);
    }
    __shared__ float red[8][3];
    if ((tid & 31)==0){ int w = tid>>5; red[w][0]=s1; red[w][1]=s2; red[w][2]=s3; }
    __syncthreads();
    float S1 = red[g*2][0]+red[g*2+1][0];
    float S2 = red[g*2][1]+red[g*2+1][1];
    float S3 = red[g*2][2]+red[g*2+1][2];
    float mu = S1*(1.f/64.f);
    float var = S2*(1.f/64.f) - mu*mu;
    float y = (ov-mu)*rsqrtf(var + 6.4e-4f)*gnw[c] + gnb[c] + S3*vf[idx];
    float xo = y * gg[idx];
    __nv_bfloat16 hv, lv;
    split_hilo(xo, hv, lv);
    xoh[idx] = hv;
    xol[idx] = lv;
}

// ---------------------------------------------------------------------------
// Launch
// ---------------------------------------------------------------------------
extern "C" void kernel_launch(void* const* d_in, const int* in_sizes, int n_in,
                              void* d_out, int out_size)
{
    const float* h      = (const float*)d_in[0];
    const float* shift  = (const float*)d_in[1];
    const float* s0     = (const float*)d_in[2];
    const float* vfirst = (const float*)d_in[3];
    const float* x_r = (const float*)d_in[4];
    const float* x_w = (const float*)d_in[5];
    const float* x_k = (const float*)d_in[6];
    const float* x_v = (const float*)d_in[7];
    const float* x_a = (const float*)d_in[8];
    const float* x_g = (const float*)d_in[9];
    const float* w0 = (const float*)d_in[10];
    const float* w1 = (const float*)d_in[11];
    const float* w2 = (const float*)d_in[12];
    const float* a0 = (const float*)d_in[13];
    const float* a1 = (const float*)d_in[14];
    const float* a2 = (const float*)d_in[15];
    const float* v0 = (const float*)d_in[16];
    const float* v1 = (const float*)d_in[17];
    const float* v2 = (const float*)d_in[18];
    const float* g1 = (const float*)d_in[19];
    const float* g2 = (const float*)d_in[20];
    const float* k_k = (const float*)d_in[21];
    const float* k_a = (const float*)d_in[22];
    const float* r_k = (const float*)d_in[23];
    const float* W_r = (const float*)d_in[24];
    const float* W_k = (const float*)d_in[25];
    const float* W_v = (const float*)d_in[26];
    const float* W_o = (const float*)d_in[27];
    const float* gnw = (const float*)d_in[28];
    const float* gnb = (const float*)d_in[29];
    float* out = (float*)d_out;

    float* S = nullptr;
    cudaGetSymbolAddress((void**)&S, g_scratch);

    float* xw    = S + (size_t)S_XW*BTC;
    float* xa    = S + (size_t)S_XA*BTC;
    float* xv    = S + (size_t)S_XV*BTC;
    float* xg    = S + (size_t)S_XG*BTC;
    float* rb    = S + (size_t)S_R*BTC;
    float* kb    = S + (size_t)S_K*BTC;
    float* vb    = S + (size_t)S_V*BTC;
    float* decay = S + (size_t)S_DECAY*BTC;
    float* asig  = S + (size_t)S_ASIG*BTC;
    float* gbuf  = S + (size_t)S_G*BTC;
    float* awb   = S + (size_t)S_AW*BTC;
    float* bwb   = S + (size_t)S_BW*BTC;
    float* kfb   = S + (size_t)S_KF*BTC;
    float* vfb   = S + (size_t)S_VF*BTC;
    float* ob    = S + (size_t)S_O*BTC;
    float* drb   = S + (size_t)S_DR*BTC;

    __nv_bfloat16* bfb = (__nv_bfloat16*)(S + BF16_BASE);
#define BF(i) (bfb + (size_t)(i)*BTC)
    __nv_bfloat16 *xrh=BF(B_XRH), *xrl=BF(B_XRL), *xkh=BF(B_XKH), *xkl=BF(B_XKL);
    __nv_bfloat16 *xvh=BF(B_XVH), *xvl=BF(B_XVL), *xoh=BF(B_XOH), *xol=BF(B_XOL);
    __nv_bfloat16 *wrh=BF(B_WRH), *wrl=BF(B_WRL), *wkh=BF(B_WKH), *wkl=BF(B_WKL);
    __nv_bfloat16 *wvh=BF(B_WVH), *wvl=BF(B_WVL), *woh=BF(B_WOH), *wol=BF(B_WOL);
#undef BF
    __nv_bfloat16* ub = (__nv_bfloat16*)(S + U_OFF);
    __nv_bfloat16 *uwh = ub,                     *uwl = uwh + (size_t)BT*64;
    __nv_bfloat16 *uah = uwl + (size_t)BT*64,    *ual = uah + (size_t)BT*64;
    __nv_bfloat16 *uvh = ual + (size_t)BT*64,    *uvl = uvh + (size_t)BT*32;
    __nv_bfloat16 *ugh = uvl + (size_t)BT*32,    *ugl = ugh + (size_t)BT*128;
    __nv_bfloat16* vtb = (__nv_bfloat16*)(S + V2T_OFF);
    __nv_bfloat16 *w2h = vtb,                    *w2l = w2h + (size_t)CC*64;
    __nv_bfloat16 *a2h = w2l + (size_t)CC*64,    *a2l = a2h + (size_t)CC*64;
    __nv_bfloat16 *v2h = a2l + (size_t)CC*64,    *v2l = v2h + (size_t)CC*32;
    __nv_bfloat16 *g2h = v2l + (size_t)CC*32,    *g2l = g2h + (size_t)CC*128;

    float* brg = S + BR_OFF;  float* krg = S + KR_OFF;

    cudaFuncSetAttribute(gemm_lora_kernel,
                         cudaFuncAttributeMaxDynamicSharedMemorySize, GEMM_SMEM);
    cudaFuncSetAttribute(stage2_hmma,
                         cudaFuncAttributeMaxDynamicSharedMemorySize, GEMM_SMEM);

    // 0a. big weight conversions
    CvtJobs cj;
    cj.x[0]=W_r; cj.hi[0]=wrh; cj.lo[0]=wrl;
    cj.x[1]=W_k; cj.hi[1]=wkh; cj.lo[1]=wkl;
    cj.x[2]=W_v; cj.hi[2]=wvh; cj.lo[2]=wvl;
    cj.x[3]=W_o; cj.hi[3]=woh; cj.lo[3]=wol;
    cvt_all_kernel<<<dim3(4096, 4), 256>>>(cj);

    // 0b. V2 transpose + hi/lo
    V2tJobs vj;
    vj.src[0]=w2; vj.dh[0]=w2h; vj.dl[0]=w2l; vj.D[0]=64;
    vj.src[1]=a2; vj.dh[1]=a2h; vj.dl[1]=a2l; vj.D[1]=64;
    vj.src[2]=v2; vj.dh[2]=v2h; vj.dl[2]=v2l; vj.D[2]=32;
    vj.src[3]=g2; vj.dh[3]=g2h; vj.dl[3]=g2l; vj.D[3]=128;
    cvt_v2t_kernel<<<dim3(1024, 4), 256>>>(vj);

    // 1. token shift + mixes
    mix_kernel<<<4096, 256>>>(h, shift, x_r, x_w, x_k, x_v, x_a, x_g,
                              xrh, xrl, xw, xkh, xkl, xv, xvh, xvl, xa, xg);

    // 2+3. FUSED: r/k/v projections + LoRA stage 1
    FusedJobs fj;
    fj.g[0] = { xrh, xrl, wrh, wrl, rb };
    fj.g[1] = { xkh, xkl, wkh, wkl, kb };
    fj.g[2] = { xvh, xvl, wvh, wvl, vb };
    fj.l[0] = { xw, w1, uwh, uwl,  64, 0, 1 };   // tanh
    fj.l[1] = { xa, a1, uah, ual,  64, 0, 0 };
    fj.l[2] = { xv, v1, uvh, uvl,  32, 0, 0 };
    fj.l[3] = { xg, g1, ugh, ugl, 128, 0, 2 };   // sigmoid
    fj.l[4] = { xg, g1, ugh, ugl, 128, 64, 2 };  // sigmoid
    gemm_lora_kernel<<<dim3(8, 16, 5), 256, GEMM_SMEM>>>(fj, 3);

    // 4. LoRA stage 2 on HMMA + fused epilogues
    S2Jobs sj;
    sj.j[0] = { uwh, uwl, w2h, w2l, w0, decay, nullptr, nullptr,  64, 0 };
    sj.j[1] = { uah, ual, a2h, a2l, a0, asig,  nullptr, nullptr,  64, 1 };
    sj.j[2] = { uvh, uvl, v2h, v2l, v0, vfb,   vb,      vfirst,   32, 2 };
    sj.j[3] = { ugh, ugl, g2h, g2l, nullptr, gbuf, nullptr, nullptr, 128, 3 };
    stage2_hmma<<<dim3(8, 16, 4), 256, GEMM_SMEM>>>(sj);

    // 5. prep + per-step scalars + dr
    prep_kernel<<<BT*HH/4, 256>>>(kb, rb, asig, decay, k_k, k_a,
                                  awb, bwb, kfb, drb, brg, krg);

    // 6. WKV7 recurrence (r9 PF-6 ring)
    wkv_kernel<<<BB*HH*4, 128>>>(drb, kfb, vfb, decay, awb, bwb, brg, krg, s0, ob);

    // 7. group norm + bonus + gate
    gn_kernel<<<BT*HH/4, 256>>>(ob, rb, kfb, vfb, gbuf, r_k, gnw, gnb, xoh, xol);

    // 8. output projection
    FusedJobs oj = fj;
    oj.g[0] = { xoh, xol, woh, wol, out };
    gemm_lora_kernel<<<dim3(8, 16, 1), 256, GEMM_SMEM>>>(oj, 1);
}